// round 1
// baseline (speedup 1.0000x reference)
#include <cuda_runtime.h>
#include <cuda_bf16.h>
#include <math.h>

// ---------------- problem constants ----------------
#define V      200000
#define E      128
#define PAD    (V-1)
#define KNN_K  32
#define BQ     2048
#define BS     5
#define NN     128
#define KT     64
#define D      256          // 2*E
#define STEPS  4
#define H      512          // 2*D
#define NR     (2*BQ + 2*BS)   // 4106 neighbor-encoder rows
#define MG     (2*NR)          // 8212 rows in the gcn GEMM

// ---------------- scratch (device globals; no allocs allowed) ----------------
__device__ float g_Agcn[(size_t)MG * D];        // [8212,256] mean vectors
__device__ float g_gcn[(size_t)MG * E];         // [8212,128] tanh(gcn) out
__device__ float g_X[(size_t)(BQ + BS) * D];    // [2053,256] gated concat (q rows 0..2047, s rows 2048..2052)
__device__ float g_T[(size_t)(BQ + BS) * H];    // [2053,512] relu hidden
__device__ float g_Y[(size_t)(BQ + BS) * D];    // [2053,256] pre-LN
__device__ float g_se[(size_t)(BQ + BS) * D];   // [2053,256] post-LN
__device__ float g_sg[D];                        // support_g
__device__ float g_Wih[(size_t)1024 * D];        // packed W_ih rows (i,f,g,o first halves)
__device__ float g_Whh[(size_t)1024 * D];        // packed W_hh rows, cols 0..255
__device__ float g_bz[1024];                     // b_ih + b_hh (packed rows)
__device__ float g_zs[1024];                     // support_g @ W_hh[:,256:].T (packed rows)
__device__ float g_zq[(size_t)BQ * 1024];        // query @ W_ih.T + bz
__device__ float g_z[(size_t)BQ * 1024];         // per-step gates
__device__ float g_c[(size_t)BQ * D];
__device__ float g_h[(size_t)BQ * D];

__device__ __forceinline__ float sigm(float x) { return 1.f / (1.f + __expf(-x)); }

// block reduce for 256 threads
__device__ __forceinline__ float blk_reduce256(float v, float* sm) {
    int t = threadIdx.x;
#pragma unroll
    for (int o = 16; o; o >>= 1) v += __shfl_xor_sync(0xffffffffu, v, o);
    if ((t & 31) == 0) sm[t >> 5] = v;
    __syncthreads();
    if (t < 32) {
        float r = (t < 8) ? sm[t] : 0.f;
#pragma unroll
        for (int o = 4; o; o >>= 1) r += __shfl_xor_sync(0xffffffffu, r, o);
        if (t == 0) sm[0] = r;
    }
    __syncthreads();
    float r = sm[0];
    __syncthreads();
    return r;
}

// ---------------- K1: neighbor encoder gather/top-k/mean ----------------
// grid: NR blocks of 256 threads. Row r -> writes g_Agcn[r] (structural) and g_Agcn[NR+r] (knn).
__global__ void nbr_kernel(const float* __restrict__ emb,
                           const int* __restrict__ query,
                           const int* __restrict__ support,
                           const int* __restrict__ qlc,
                           const int* __restrict__ qrc,
                           const int* __restrict__ slc,
                           const int* __restrict__ src,
                           const int* __restrict__ knn)
{
    int r = blockIdx.x;
    int tid = threadIdx.x, lane = tid & 31, warp = tid >> 5;

    const int* conn; int eid;
    if (r < BQ)               { eid = query[2*r];                 conn = qlc + (size_t)r*NN*2; }
    else if (r < 2*BQ)        { int b=r-BQ;   eid = query[2*b+1]; conn = qrc + (size_t)b*NN*2; }
    else if (r < 2*BQ+BS)     { int b=r-2*BQ; eid = support[2*b]; conn = slc + (size_t)b*NN*2; }
    else                      { int b=r-2*BQ-BS; eid = support[2*b+1]; conn = src + (size_t)b*NN*2; }
    if (eid < 0 || eid >= V) eid = PAD;

    __shared__ __align__(16) float cs[E];
    __shared__ float sims[NN];
    __shared__ float sumE[E], sumR[E], sumK[E];
    __shared__ int idsR[NN], idsE[NN], kid[KT], sel[KNN_K];
    __shared__ int selcnt;
    __shared__ float s_cn;

    if (tid < E) { cs[tid] = emb[(size_t)eid*E + tid]; sumE[tid]=0.f; sumR[tid]=0.f; sumK[tid]=0.f; }
    if (tid < NN) {
        int a = conn[2*tid], b = conn[2*tid+1];
        idsR[tid] = min(max(a,0), V-1);
        idsE[tid] = min(max(b,0), V-1);
    }
    if (tid < KT) { int kk = knn[(size_t)eid*KT + tid]; if (kk < 0 || kk >= V) kk = PAD; kid[tid] = kk; }
    if (tid == 0) selcnt = 0;
    __syncthreads();

    if (warp == 0) {
        float4 c = ((const float4*)cs)[lane];
        float s = c.x*c.x + c.y*c.y + c.z*c.z + c.w*c.w;
#pragma unroll
        for (int o = 16; o; o >>= 1) s += __shfl_xor_sync(0xffffffffu, s, o);
        if (lane == 0) s_cn = fmaxf(sqrtf(s), 1e-8f);
    }
    __syncthreads();
    float cn = s_cn;
    float4 c4 = ((const float4*)cs)[lane];

    // sims vs ent neighbors
    for (int n = warp; n < NN; n += 8) {
        const float4* e4 = (const float4*)(emb + (size_t)idsE[n]*E);
        float4 v = e4[lane];
        float dd = v.x*c4.x + v.y*c4.y + v.z*c4.z + v.w*c4.w;
        float qq = v.x*v.x + v.y*v.y + v.z*v.z + v.w*v.w;
#pragma unroll
        for (int o = 16; o; o >>= 1) { dd += __shfl_xor_sync(0xffffffffu, dd, o);
                                       qq += __shfl_xor_sync(0xffffffffu, qq, o); }
        if (lane == 0) sims[n] = dd / (cn * fmaxf(sqrtf(qq), 1e-8f));
    }
    __syncthreads();

    // stable top-32 of 128 via rank counting (matches jax.lax.top_k tie-break)
    if (tid < NN) {
        float sn = sims[tid]; int cnt = 0;
#pragma unroll 4
        for (int m = 0; m < NN; m++) {
            float sm = sims[m];
            cnt += (sm > sn) || (sm == sn && m < tid);
        }
        if (cnt < KNN_K) { int p = atomicAdd(&selcnt, 1); sel[p] = tid; }
    }
    __syncthreads();

    // accumulate mean of selected ent + rel embeddings
    {
        float4 aE = make_float4(0,0,0,0), aR = make_float4(0,0,0,0);
        for (int p = warp; p < KNN_K; p += 8) {
            int n = sel[p];
            float4 v = ((const float4*)(emb + (size_t)idsE[n]*E))[lane];
            float4 w = ((const float4*)(emb + (size_t)idsR[n]*E))[lane];
            aE.x += v.x; aE.y += v.y; aE.z += v.z; aE.w += v.w;
            aR.x += w.x; aR.y += w.y; aR.z += w.z; aR.w += w.w;
        }
        atomicAdd(&sumE[lane*4+0], aE.x); atomicAdd(&sumE[lane*4+1], aE.y);
        atomicAdd(&sumE[lane*4+2], aE.z); atomicAdd(&sumE[lane*4+3], aE.w);
        atomicAdd(&sumR[lane*4+0], aR.x); atomicAdd(&sumR[lane*4+1], aR.y);
        atomicAdd(&sumR[lane*4+2], aR.z); atomicAdd(&sumR[lane*4+3], aR.w);
    }
    __syncthreads();
    if (tid == 0) selcnt = 0;

    // knn branch sims (64 candidates)
    for (int n = warp; n < KT; n += 8) {
        const float4* e4 = (const float4*)(emb + (size_t)kid[n]*E);
        float4 v = e4[lane];
        float dd = v.x*c4.x + v.y*c4.y + v.z*c4.z + v.w*c4.w;
        float qq = v.x*v.x + v.y*v.y + v.z*v.z + v.w*v.w;
#pragma unroll
        for (int o = 16; o; o >>= 1) { dd += __shfl_xor_sync(0xffffffffu, dd, o);
                                       qq += __shfl_xor_sync(0xffffffffu, qq, o); }
        if (lane == 0) sims[n] = dd / (cn * fmaxf(sqrtf(qq), 1e-8f));
    }
    __syncthreads();

    if (tid < KT) {
        float sn = sims[tid]; int cnt = 0;
#pragma unroll 4
        for (int m = 0; m < KT; m++) {
            float sm = sims[m];
            cnt += (sm > sn) || (sm == sn && m < tid);
        }
        if (cnt < KNN_K) { int p = atomicAdd(&selcnt, 1); sel[p] = tid; }
    }
    __syncthreads();

    {
        float4 aK = make_float4(0,0,0,0);
        for (int p = warp; p < KNN_K; p += 8) {
            int n = sel[p];
            float4 v = ((const float4*)(emb + (size_t)kid[n]*E))[lane];
            aK.x += v.x; aK.y += v.y; aK.z += v.z; aK.w += v.w;
        }
        atomicAdd(&sumK[lane*4+0], aK.x); atomicAdd(&sumK[lane*4+1], aK.y);
        atomicAdd(&sumK[lane*4+2], aK.z); atomicAdd(&sumK[lane*4+3], aK.w);
    }
    __syncthreads();

    if (tid < E) {
        const float inv = 1.f / (float)KNN_K;
        size_t o1 = (size_t)r * D;
        g_Agcn[o1 + tid]       = sumR[tid] * inv;   // cat first half = rel
        g_Agcn[o1 + E + tid]   = sumE[tid] * inv;   // cat second half = ent
        size_t o2 = (size_t)(NR + r) * D;
        g_Agcn[o2 + tid]       = 0.f;               // pad_rel == emb[PAD] == 0
        g_Agcn[o2 + E + tid]   = sumK[tid] * inv;
    }
}

// ---------------- generic tiled SGEMM: C = act(A[M,K] @ B[N,K]^T + bias + res) ----------------
// ACT: 0=none, 1=relu, 2=tanh. N multiple of 64, K multiple of 16.
template<int ACT>
__global__ void gemm_kernel(const float* __restrict__ A, const float* __restrict__ B,
                            const float* __restrict__ bias, const float* __restrict__ res,
                            float* __restrict__ C, int M, int N, int K)
{
    const int BM = 64, BN = 64, BK = 16;
    __shared__ __align__(16) float As[BK][BM];
    __shared__ __align__(16) float Bs[BK][BN];
    int tid = threadIdx.x;              // 256 threads
    int m0 = blockIdx.y * BM, n0 = blockIdx.x * BN;
    int tx = tid & 15, ty = tid >> 4;
    int lm = tid >> 2;                  // 0..63 tile row
    int lk = (tid & 3) * 4;             // 0,4,8,12

    float acc[4][4];
#pragma unroll
    for (int i = 0; i < 4; i++)
#pragma unroll
        for (int j = 0; j < 4; j++) acc[i][j] = 0.f;

    for (int k0 = 0; k0 < K; k0 += BK) {
        float4 a = make_float4(0,0,0,0), b = make_float4(0,0,0,0);
        int gm = m0 + lm, gn = n0 + lm;
        if (gm < M) a = *(const float4*)(A + (size_t)gm * K + k0 + lk);
        if (gn < N) b = *(const float4*)(B + (size_t)gn * K + k0 + lk);
        As[lk+0][lm] = a.x; As[lk+1][lm] = a.y; As[lk+2][lm] = a.z; As[lk+3][lm] = a.w;
        Bs[lk+0][lm] = b.x; Bs[lk+1][lm] = b.y; Bs[lk+2][lm] = b.z; Bs[lk+3][lm] = b.w;
        __syncthreads();
#pragma unroll
        for (int kk = 0; kk < BK; kk++) {
            float4 av = *(const float4*)(&As[kk][ty * 4]);
            float4 bv = *(const float4*)(&Bs[kk][tx * 4]);
            float ar[4] = {av.x, av.y, av.z, av.w};
            float br[4] = {bv.x, bv.y, bv.z, bv.w};
#pragma unroll
            for (int i = 0; i < 4; i++)
#pragma unroll
                for (int j = 0; j < 4; j++) acc[i][j] += ar[i] * br[j];
        }
        __syncthreads();
    }

#pragma unroll
    for (int i = 0; i < 4; i++) {
        int row = m0 + ty * 4 + i;
        if (row >= M) continue;
#pragma unroll
        for (int j = 0; j < 4; j++) {
            int col = n0 + tx * 4 + j;
            float v = acc[i][j] + bias[col];
            if (res) v += res[(size_t)row * N + col];
            if (ACT == 1) v = fmaxf(v, 0.f);
            if (ACT == 2) v = tanhf(v);
            C[(size_t)row * N + col] = v;
        }
    }
}

// ---------------- K3: sigmoid gate + concat into X ----------------
__global__ void gate_kernel(const float* __restrict__ gate_W, const float* __restrict__ gate_b)
{
    __shared__ float sm[8];
    int r = blockIdx.x, t = threadIdx.x;  // 256 threads, 128 active features
    float s = 0.f, k = 0.f, part = 0.f;
    if (t < E) {
        s = g_gcn[(size_t)r * E + t];
        k = g_gcn[(size_t)(NR + r) * E + t];
        part = s * gate_W[t] + k * gate_W[E + t];
    }
    float ain = blk_reduce256(part, sm);
    float a = sigm(ain + gate_b[0]);
    if (t < E) {
        float f = (1.f - a) * s + a * k;
        size_t dst;
        if (r < BQ)            dst = (size_t)r * D + t;                 // ql -> X[b][0:128]
        else if (r < 2*BQ)     dst = (size_t)(r - BQ) * D + E + t;      // qr -> X[b][128:256]
        else if (r < 2*BQ+BS)  dst = (size_t)(BQ + r - 2*BQ) * D + t;   // sl
        else                   dst = (size_t)(BQ + r - 2*BQ - BS) * D + E + t; // sr
        g_X[dst] = f;
    }
}

// ---------------- K6: layernorm rows of g_Y -> g_se ----------------
__global__ void ln_kernel(const float* __restrict__ ln_g, const float* __restrict__ ln_b)
{
    __shared__ float sm[8];
    int r = blockIdx.x, t = threadIdx.x; // 256 threads == D
    float x = g_Y[(size_t)r * D + t];
    float mu = blk_reduce256(x, sm) * (1.f / D);
    float d = x - mu;
    float var = blk_reduce256(d * d, sm) * (1.f / D);
    g_se[(size_t)r * D + t] = d * rsqrtf(var + 1e-5f) * ln_g[t] + ln_b[t];
}

// ---------------- K7: support_g = mean of 5 support rows ----------------
__global__ void sg_kernel()
{
    int t = threadIdx.x; // 256
    float s = 0.f;
#pragma unroll
    for (int i = 0; i < BS; i++) s += g_se[(size_t)(BQ + i) * D + t];
    g_sg[t] = s * (1.f / BS);
}

// ---------------- K8: pack LSTM weights (live gate halves only) + zs, bz ----------------
__global__ void pack_kernel(const float* __restrict__ W_ih, const float* __restrict__ W_hh,
                            const float* __restrict__ b_ih, const float* __restrict__ b_hh)
{
    __shared__ float sm[8];
    int p = blockIdx.x;          // 0..1023 packed row
    int t = threadIdx.x;         // 256
    int blk = p >> 8, e = p & 255;
    int orig = blk * 512 + e;    // i:0..255 f:512..767 g:1024..1279 o:1536..1791
    g_Wih[(size_t)p * D + t] = W_ih[(size_t)orig * D + t];
    g_Whh[(size_t)p * D + t] = W_hh[(size_t)orig * H + t];
    float part = W_hh[(size_t)orig * H + D + t] * g_sg[t];
    float zsv = blk_reduce256(part, sm);
    if (t == 0) {
        g_zs[p] = zsv;
        g_bz[p] = b_ih[orig] + b_hh[orig];
    }
}

// ---------------- LSTM elementwise steps ----------------
__global__ void lstm_step1()
{
    int idx = blockIdx.x * blockDim.x + threadIdx.x;  // BQ*D
    int b = idx >> 8, e = idx & 255;
    const float* z = g_z + 0;  // unused
    (void)z;
    const float* zq = g_zq + (size_t)b * 1024;
    float zi = zq[e], zg = zq[512 + e], zo = zq[768 + e];
    float c = sigm(zi) * tanhf(zg);               // c_prev = 0
    g_c[idx] = c;
    g_h[idx] = g_se[idx] + sigm(zo) * tanhf(c);
}

__global__ void lstm_step()
{
    int idx = blockIdx.x * blockDim.x + threadIdx.x;
    int b = idx >> 8, e = idx & 255;
    const float* z = g_z + (size_t)b * 1024;
    float zi = z[e], zf = z[256 + e], zg = z[512 + e], zo = z[768 + e];
    float c = sigm(zf) * g_c[idx] + sigm(zi) * tanhf(zg);
    g_c[idx] = c;
    g_h[idx] = g_se[idx] + sigm(zo) * tanhf(c);
}

// ---------------- K13: normalized cosine output ----------------
__global__ void final_kernel(float* __restrict__ out)
{
    __shared__ float sm[8];
    int b = blockIdx.x, t = threadIdx.x; // 256
    float hv = g_h[(size_t)b * D + t];
    float sv = g_sg[t];
    float dot = blk_reduce256(hv * sv, sm);
    float hh  = blk_reduce256(hv * hv, sm);
    float ss  = blk_reduce256(sv * sv, sm);
    if (t == 0)
        out[b] = dot / (fmaxf(sqrtf(hh), 1e-12f) * fmaxf(sqrtf(ss), 1e-12f));
}

// ---------------- launch ----------------
extern "C" void kernel_launch(void* const* d_in, const int* in_sizes, int n_in,
                              void* d_out, int out_size)
{
    const float* emb    = (const float*)d_in[0];
    const float* gcn_W  = (const float*)d_in[1];
    const float* gcn_wb = (const float*)d_in[2];
    const float* gate_W = (const float*)d_in[3];
    const float* gate_b = (const float*)d_in[4];
    const float* se_w1  = (const float*)d_in[5];
    const float* se_b1  = (const float*)d_in[6];
    const float* se_w2  = (const float*)d_in[7];
    const float* se_b2  = (const float*)d_in[8];
    const float* ln_g   = (const float*)d_in[9];
    const float* ln_b   = (const float*)d_in[10];
    const float* W_ih   = (const float*)d_in[11];
    const float* W_hh   = (const float*)d_in[12];
    const float* b_ih   = (const float*)d_in[13];
    const float* b_hh   = (const float*)d_in[14];
    const int*   query  = (const int*)d_in[15];
    const int*   support= (const int*)d_in[16];
    const int*   qlc    = (const int*)d_in[17];
    const int*   qrc    = (const int*)d_in[19];
    const int*   slc    = (const int*)d_in[21];
    const int*   src    = (const int*)d_in[23];
    const int*   knn    = (const int*)d_in[25];
    float* out = (float*)d_out;

    float *Agcn, *gcn, *X, *T, *Y, *se, *h, *Wih, *Whh, *bz, *zs, *zq, *z;
    cudaGetSymbolAddress((void**)&Agcn, g_Agcn);
    cudaGetSymbolAddress((void**)&gcn,  g_gcn);
    cudaGetSymbolAddress((void**)&X,    g_X);
    cudaGetSymbolAddress((void**)&T,    g_T);
    cudaGetSymbolAddress((void**)&Y,    g_Y);
    cudaGetSymbolAddress((void**)&se,   g_se);
    cudaGetSymbolAddress((void**)&h,    g_h);
    cudaGetSymbolAddress((void**)&Wih,  g_Wih);
    cudaGetSymbolAddress((void**)&Whh,  g_Whh);
    cudaGetSymbolAddress((void**)&bz,   g_bz);
    cudaGetSymbolAddress((void**)&zs,   g_zs);
    cudaGetSymbolAddress((void**)&zq,   g_zq);
    cudaGetSymbolAddress((void**)&z,    g_z);

    // K1: neighbor gather / top-k / means
    nbr_kernel<<<NR, 256>>>(emb, query, support, qlc, qrc, slc, src, knn);

    // K2: gcn GEMM  [8212,256] @ [128,256]^T -> tanh
    {
        dim3 grid((E + 63) / 64, (MG + 63) / 64);
        gemm_kernel<2><<<grid, 256>>>(Agcn, gcn_W, gcn_wb, nullptr, gcn, MG, E, D);
    }

    // K3: gate + concat
    gate_kernel<<<NR, 256>>>(gate_W, gate_b);

    // K4: se layer 1  [2053,256] @ [512,256]^T -> relu
    {
        dim3 grid((H + 63) / 64, (BQ + BS + 63) / 64);
        gemm_kernel<1><<<grid, 256>>>(X, se_w1, se_b1, nullptr, T, BQ + BS, H, D);
    }
    // K5: se layer 2  [2053,512] @ [256,512]^T + b2 + X
    {
        dim3 grid((D + 63) / 64, (BQ + BS + 63) / 64);
        gemm_kernel<0><<<grid, 256>>>(T, se_w2, se_b2, X, Y, BQ + BS, D, H);
    }
    // K6: layernorm
    ln_kernel<<<BQ + BS, 256>>>(ln_g, ln_b);
    // K7: support_g
    sg_kernel<<<1, 256>>>();
    // K8: pack LSTM weights + zs/bz
    pack_kernel<<<1024, 256>>>(W_ih, W_hh, b_ih, b_hh);

    // K9: zq = query_g @ Wih_p^T + bz   [2048,1024]
    {
        dim3 grid(1024 / 64, BQ / 64);
        gemm_kernel<0><<<grid, 256>>>(se, Wih, bz, nullptr, zq, BQ, 1024, D);
    }
    // step 1 (h_r = 0)
    lstm_step1<<<(BQ * D) / 256, 256>>>();
    // steps 2..4: z = zq + zs + h @ Whh_p^T
    for (int s = 1; s < STEPS; s++) {
        dim3 grid(1024 / 64, BQ / 64);
        gemm_kernel<0><<<grid, 256>>>(h, Whh, zs, zq, z, BQ, 1024, D);
        lstm_step<<<(BQ * D) / 256, 256>>>();
    }

    // K13: cosine similarity output
    final_kernel<<<BQ, 256>>>(out);
}

// round 2
// speedup vs baseline: 1.1617x; 1.1617x over previous
#include <cuda_runtime.h>
#include <cuda_bf16.h>
#include <math.h>

// ---------------- problem constants ----------------
#define V      200000
#define E      128
#define PAD    (V-1)
#define KNN_K  32
#define BQ     2048
#define BS     5
#define NN     128
#define KT     64
#define D      256          // 2*E
#define STEPS  4
#define H      512          // 2*D
#define NR     (2*BQ + 2*BS)   // 4106 neighbor-encoder rows
#define MG     (2*NR)          // 8212 rows in the gcn GEMM

// ---------------- scratch (device globals; no allocs allowed) ----------------
__device__ float g_Agcn[(size_t)MG * D];        // [8212,256] mean vectors
__device__ float g_gcn[(size_t)MG * E];         // [8212,128] tanh(gcn) out
__device__ float g_X[(size_t)(BQ + BS) * D];    // [2053,256] gated concat
__device__ float g_T[(size_t)(BQ + BS) * H];    // [2053,512] relu hidden
__device__ float g_Y[(size_t)(BQ + BS) * D];    // [2053,256] pre-LN
__device__ float g_se[(size_t)(BQ + BS) * D];   // [2053,256] post-LN
__device__ float g_sg[D];                        // support_g
__device__ float g_Wih[(size_t)1024 * D];        // packed W_ih rows (live gate halves)
__device__ float g_Whh[(size_t)1024 * D];        // packed W_hh rows, cols 0..255
__device__ float g_bz[1024];                     // b_ih + b_hh (packed rows)
__device__ float g_zs[1024];                     // support_g @ W_hh[:,256:].T
__device__ float g_zq[(size_t)BQ * 1024];        // query @ W_ih.T + bz
__device__ float g_z[(size_t)BQ * 1024];         // per-step gates
__device__ float g_c[(size_t)BQ * D];
__device__ float g_h[(size_t)BQ * D];

__device__ __forceinline__ float sigm(float x) { return 1.f / (1.f + __expf(-x)); }

// block reduce for 256 threads
__device__ __forceinline__ float blk_reduce256(float v, float* sm) {
    int t = threadIdx.x;
#pragma unroll
    for (int o = 16; o; o >>= 1) v += __shfl_xor_sync(0xffffffffu, v, o);
    if ((t & 31) == 0) sm[t >> 5] = v;
    __syncthreads();
    if (t < 32) {
        float r = (t < 8) ? sm[t] : 0.f;
#pragma unroll
        for (int o = 4; o; o >>= 1) r += __shfl_xor_sync(0xffffffffu, r, o);
        if (t == 0) sm[0] = r;
    }
    __syncthreads();
    float r = sm[0];
    __syncthreads();
    return r;
}

// ---------------- K1: neighbor encoder gather/top-k/mean ----------------
__global__ void nbr_kernel(const float* __restrict__ emb,
                           const int* __restrict__ query,
                           const int* __restrict__ support,
                           const int* __restrict__ qlc,
                           const int* __restrict__ qrc,
                           const int* __restrict__ slc,
                           const int* __restrict__ src,
                           const int* __restrict__ knn)
{
    int r = blockIdx.x;
    int tid = threadIdx.x, lane = tid & 31, warp = tid >> 5;

    const int* conn; int eid;
    if (r < BQ)               { eid = query[2*r];                 conn = qlc + (size_t)r*NN*2; }
    else if (r < 2*BQ)        { int b=r-BQ;   eid = query[2*b+1]; conn = qrc + (size_t)b*NN*2; }
    else if (r < 2*BQ+BS)     { int b=r-2*BQ; eid = support[2*b]; conn = slc + (size_t)b*NN*2; }
    else                      { int b=r-2*BQ-BS; eid = support[2*b+1]; conn = src + (size_t)b*NN*2; }
    if (eid < 0 || eid >= V) eid = PAD;

    __shared__ __align__(16) float cs[E];
    __shared__ float sims[NN];
    __shared__ float sumE[E], sumR[E], sumK[E];
    __shared__ int idsR[NN], idsE[NN], kid[KT], sel[KNN_K];
    __shared__ int selcnt;
    __shared__ float s_cn;

    if (tid < E) { cs[tid] = emb[(size_t)eid*E + tid]; sumE[tid]=0.f; sumR[tid]=0.f; sumK[tid]=0.f; }
    if (tid < NN) {
        int a = conn[2*tid], b = conn[2*tid+1];
        idsR[tid] = min(max(a,0), V-1);
        idsE[tid] = min(max(b,0), V-1);
    }
    if (tid < KT) { int kk = knn[(size_t)eid*KT + tid]; if (kk < 0 || kk >= V) kk = PAD; kid[tid] = kk; }
    if (tid == 0) selcnt = 0;
    __syncthreads();

    if (warp == 0) {
        float4 c = ((const float4*)cs)[lane];
        float s = c.x*c.x + c.y*c.y + c.z*c.z + c.w*c.w;
#pragma unroll
        for (int o = 16; o; o >>= 1) s += __shfl_xor_sync(0xffffffffu, s, o);
        if (lane == 0) s_cn = fmaxf(sqrtf(s), 1e-8f);
    }
    __syncthreads();
    float cn = s_cn;
    float4 c4 = ((const float4*)cs)[lane];

    for (int n = warp; n < NN; n += 8) {
        const float4* e4 = (const float4*)(emb + (size_t)idsE[n]*E);
        float4 v = e4[lane];
        float dd = v.x*c4.x + v.y*c4.y + v.z*c4.z + v.w*c4.w;
        float qq = v.x*v.x + v.y*v.y + v.z*v.z + v.w*v.w;
#pragma unroll
        for (int o = 16; o; o >>= 1) { dd += __shfl_xor_sync(0xffffffffu, dd, o);
                                       qq += __shfl_xor_sync(0xffffffffu, qq, o); }
        if (lane == 0) sims[n] = dd / (cn * fmaxf(sqrtf(qq), 1e-8f));
    }
    __syncthreads();

    if (tid < NN) {
        float sn = sims[tid]; int cnt = 0;
#pragma unroll 4
        for (int m = 0; m < NN; m++) {
            float sm = sims[m];
            cnt += (sm > sn) || (sm == sn && m < tid);
        }
        if (cnt < KNN_K) { int p = atomicAdd(&selcnt, 1); sel[p] = tid; }
    }
    __syncthreads();

    {
        float4 aE = make_float4(0,0,0,0), aR = make_float4(0,0,0,0);
        for (int p = warp; p < KNN_K; p += 8) {
            int n = sel[p];
            float4 v = ((const float4*)(emb + (size_t)idsE[n]*E))[lane];
            float4 w = ((const float4*)(emb + (size_t)idsR[n]*E))[lane];
            aE.x += v.x; aE.y += v.y; aE.z += v.z; aE.w += v.w;
            aR.x += w.x; aR.y += w.y; aR.z += w.z; aR.w += w.w;
        }
        atomicAdd(&sumE[lane*4+0], aE.x); atomicAdd(&sumE[lane*4+1], aE.y);
        atomicAdd(&sumE[lane*4+2], aE.z); atomicAdd(&sumE[lane*4+3], aE.w);
        atomicAdd(&sumR[lane*4+0], aR.x); atomicAdd(&sumR[lane*4+1], aR.y);
        atomicAdd(&sumR[lane*4+2], aR.z); atomicAdd(&sumR[lane*4+3], aR.w);
    }
    __syncthreads();
    if (tid == 0) selcnt = 0;

    for (int n = warp; n < KT; n += 8) {
        const float4* e4 = (const float4*)(emb + (size_t)kid[n]*E);
        float4 v = e4[lane];
        float dd = v.x*c4.x + v.y*c4.y + v.z*c4.z + v.w*c4.w;
        float qq = v.x*v.x + v.y*v.y + v.z*v.z + v.w*v.w;
#pragma unroll
        for (int o = 16; o; o >>= 1) { dd += __shfl_xor_sync(0xffffffffu, dd, o);
                                       qq += __shfl_xor_sync(0xffffffffu, qq, o); }
        if (lane == 0) sims[n] = dd / (cn * fmaxf(sqrtf(qq), 1e-8f));
    }
    __syncthreads();

    if (tid < KT) {
        float sn = sims[tid]; int cnt = 0;
#pragma unroll 4
        for (int m = 0; m < KT; m++) {
            float sm = sims[m];
            cnt += (sm > sn) || (sm == sn && m < tid);
        }
        if (cnt < KNN_K) { int p = atomicAdd(&selcnt, 1); sel[p] = tid; }
    }
    __syncthreads();

    {
        float4 aK = make_float4(0,0,0,0);
        for (int p = warp; p < KNN_K; p += 8) {
            int n = sel[p];
            float4 v = ((const float4*)(emb + (size_t)kid[n]*E))[lane];
            aK.x += v.x; aK.y += v.y; aK.z += v.z; aK.w += v.w;
        }
        atomicAdd(&sumK[lane*4+0], aK.x); atomicAdd(&sumK[lane*4+1], aK.y);
        atomicAdd(&sumK[lane*4+2], aK.z); atomicAdd(&sumK[lane*4+3], aK.w);
    }
    __syncthreads();

    if (tid < E) {
        const float inv = 1.f / (float)KNN_K;
        size_t o1 = (size_t)r * D;
        g_Agcn[o1 + tid]       = sumR[tid] * inv;
        g_Agcn[o1 + E + tid]   = sumE[tid] * inv;
        size_t o2 = (size_t)(NR + r) * D;
        g_Agcn[o2 + tid]       = 0.f;               // pad_rel == emb[PAD] == 0
        g_Agcn[o2 + E + tid]   = sumK[tid] * inv;
    }
}

// ---------------- high-AI tiled SGEMM: C = act(A[M,K] @ B[N,K]^T + bias [+ res]) ----------------
// BM in {128,64}, BN=64, BK=16, 256 threads, thread tile (BM/16)x4.
// Double-buffered smem + register-staged prefetch. N % 64 == 0, K % 16 == 0.
template<int ACT, int BM>
__global__ __launch_bounds__(256)
void gemm_kernel(const float* __restrict__ A, const float* __restrict__ B,
                 const float* __restrict__ bias, const float* __restrict__ res,
                 float* __restrict__ C, int M, int N, int K)
{
    constexpr int BN = 64, BK = 16;
    constexpr int TM = BM / 16;                 // 8 or 4 rows per thread
    __shared__ __align__(16) float As[2][BK][BM];
    __shared__ __align__(16) float Bs[2][BK][BN];

    const int tid = threadIdx.x;
    const int tx = tid & 15, ty = tid >> 4;
    const int m0 = blockIdx.y * BM, n0 = blockIdx.x * BN;

    // global->reg load mapping
    int ar, ak;
    if (BM == 128) { ar = tid >> 1; ak = (tid & 1) * 8; }
    else           { ar = tid >> 2; ak = (tid & 3) * 4; }
    const int br = tid >> 2, bk = (tid & 3) * 4;

    const bool aval = (m0 + ar) < M;
    const float* Ap = A + (size_t)(aval ? (m0 + ar) : 0) * K + ak;
    const float* Bp = B + (size_t)(n0 + br) * K + bk;

    float acc[TM][4];
#pragma unroll
    for (int i = 0; i < TM; i++)
#pragma unroll
        for (int j = 0; j < 4; j++) acc[i][j] = 0.f;

    float4 ra0 = make_float4(0,0,0,0), ra1 = make_float4(0,0,0,0), rb;

    // prologue: fetch k-tile 0
    if (aval) {
        ra0 = *(const float4*)(Ap);
        if (BM == 128) ra1 = *(const float4*)(Ap + 4);
    }
    rb = *(const float4*)(Bp);

    // deposit into buffer 0
    {
        As[0][ak+0][ar] = ra0.x; As[0][ak+1][ar] = ra0.y;
        As[0][ak+2][ar] = ra0.z; As[0][ak+3][ar] = ra0.w;
        if (BM == 128) {
            As[0][ak+4][ar] = ra1.x; As[0][ak+5][ar] = ra1.y;
            As[0][ak+6][ar] = ra1.z; As[0][ak+7][ar] = ra1.w;
        }
        Bs[0][bk+0][br] = rb.x; Bs[0][bk+1][br] = rb.y;
        Bs[0][bk+2][br] = rb.z; Bs[0][bk+3][br] = rb.w;
    }
    __syncthreads();

    int cur = 0;
    for (int k0 = BK; k0 < K; k0 += BK) {
        // prefetch next k-tile into registers (latency hidden behind compute)
        if (aval) {
            ra0 = *(const float4*)(Ap + k0);
            if (BM == 128) ra1 = *(const float4*)(Ap + k0 + 4);
        }
        rb = *(const float4*)(Bp + k0);

        // compute on current buffer
#pragma unroll
        for (int kk = 0; kk < BK; kk++) {
            float4 bv = *(const float4*)(&Bs[cur][kk][tx * 4]);
#pragma unroll
            for (int h = 0; h < TM / 4; h++) {
                float4 av = *(const float4*)(&As[cur][kk][ty * TM + h * 4]);
                float arr[4] = {av.x, av.y, av.z, av.w};
#pragma unroll
                for (int i = 0; i < 4; i++) {
                    acc[h*4+i][0] += arr[i] * bv.x;
                    acc[h*4+i][1] += arr[i] * bv.y;
                    acc[h*4+i][2] += arr[i] * bv.z;
                    acc[h*4+i][3] += arr[i] * bv.w;
                }
            }
        }

        // deposit prefetched tile into the other buffer
        int nxt = cur ^ 1;
        As[nxt][ak+0][ar] = ra0.x; As[nxt][ak+1][ar] = ra0.y;
        As[nxt][ak+2][ar] = ra0.z; As[nxt][ak+3][ar] = ra0.w;
        if (BM == 128) {
            As[nxt][ak+4][ar] = ra1.x; As[nxt][ak+5][ar] = ra1.y;
            As[nxt][ak+6][ar] = ra1.z; As[nxt][ak+7][ar] = ra1.w;
        }
        Bs[nxt][bk+0][br] = rb.x; Bs[nxt][bk+1][br] = rb.y;
        Bs[nxt][bk+2][br] = rb.z; Bs[nxt][bk+3][br] = rb.w;
        __syncthreads();
        cur = nxt;
    }

    // final tile
#pragma unroll
    for (int kk = 0; kk < BK; kk++) {
        float4 bv = *(const float4*)(&Bs[cur][kk][tx * 4]);
#pragma unroll
        for (int h = 0; h < TM / 4; h++) {
            float4 av = *(const float4*)(&As[cur][kk][ty * TM + h * 4]);
            float arr[4] = {av.x, av.y, av.z, av.w};
#pragma unroll
            for (int i = 0; i < 4; i++) {
                acc[h*4+i][0] += arr[i] * bv.x;
                acc[h*4+i][1] += arr[i] * bv.y;
                acc[h*4+i][2] += arr[i] * bv.z;
                acc[h*4+i][3] += arr[i] * bv.w;
            }
        }
    }

    // epilogue (vectorized)
    const int col = n0 + tx * 4;
    float4 bb = *(const float4*)(bias + col);
#pragma unroll
    for (int i = 0; i < TM; i++) {
        int row = m0 + ty * TM + i;
        if (row >= M) continue;
        float4 v;
        v.x = acc[i][0] + bb.x; v.y = acc[i][1] + bb.y;
        v.z = acc[i][2] + bb.z; v.w = acc[i][3] + bb.w;
        if (res) {
            float4 rr = *(const float4*)(res + (size_t)row * N + col);
            v.x += rr.x; v.y += rr.y; v.z += rr.z; v.w += rr.w;
        }
        if (ACT == 1) { v.x = fmaxf(v.x,0.f); v.y = fmaxf(v.y,0.f); v.z = fmaxf(v.z,0.f); v.w = fmaxf(v.w,0.f); }
        if (ACT == 2) { v.x = tanhf(v.x); v.y = tanhf(v.y); v.z = tanhf(v.z); v.w = tanhf(v.w); }
        *(float4*)(C + (size_t)row * N + col) = v;
    }
}

// ---------------- K3: sigmoid gate + concat into X ----------------
__global__ void gate_kernel(const float* __restrict__ gate_W, const float* __restrict__ gate_b)
{
    __shared__ float sm[8];
    int r = blockIdx.x, t = threadIdx.x;
    float s = 0.f, k = 0.f, part = 0.f;
    if (t < E) {
        s = g_gcn[(size_t)r * E + t];
        k = g_gcn[(size_t)(NR + r) * E + t];
        part = s * gate_W[t] + k * gate_W[E + t];
    }
    float ain = blk_reduce256(part, sm);
    float a = sigm(ain + gate_b[0]);
    if (t < E) {
        float f = (1.f - a) * s + a * k;
        size_t dst;
        if (r < BQ)            dst = (size_t)r * D + t;
        else if (r < 2*BQ)     dst = (size_t)(r - BQ) * D + E + t;
        else if (r < 2*BQ+BS)  dst = (size_t)(BQ + r - 2*BQ) * D + t;
        else                   dst = (size_t)(BQ + r - 2*BQ - BS) * D + E + t;
        g_X[dst] = f;
    }
}

// ---------------- K6: layernorm rows of g_Y -> g_se ----------------
__global__ void ln_kernel(const float* __restrict__ ln_g, const float* __restrict__ ln_b)
{
    __shared__ float sm[8];
    int r = blockIdx.x, t = threadIdx.x;
    float x = g_Y[(size_t)r * D + t];
    float mu = blk_reduce256(x, sm) * (1.f / D);
    float d = x - mu;
    float var = blk_reduce256(d * d, sm) * (1.f / D);
    g_se[(size_t)r * D + t] = d * rsqrtf(var + 1e-5f) * ln_g[t] + ln_b[t];
}

// ---------------- K7: support_g = mean of 5 support rows ----------------
__global__ void sg_kernel()
{
    int t = threadIdx.x;
    float s = 0.f;
#pragma unroll
    for (int i = 0; i < BS; i++) s += g_se[(size_t)(BQ + i) * D + t];
    g_sg[t] = s * (1.f / BS);
}

// ---------------- K8: pack LSTM weights + zs, bz ----------------
__global__ void pack_kernel(const float* __restrict__ W_ih, const float* __restrict__ W_hh,
                            const float* __restrict__ b_ih, const float* __restrict__ b_hh)
{
    __shared__ float sm[8];
    int p = blockIdx.x;
    int t = threadIdx.x;
    int blk = p >> 8, e = p & 255;
    int orig = blk * 512 + e;
    g_Wih[(size_t)p * D + t] = W_ih[(size_t)orig * D + t];
    g_Whh[(size_t)p * D + t] = W_hh[(size_t)orig * H + t];
    float part = W_hh[(size_t)orig * H + D + t] * g_sg[t];
    float zsv = blk_reduce256(part, sm);
    if (t == 0) {
        g_zs[p] = zsv;
        g_bz[p] = b_ih[orig] + b_hh[orig];
    }
}

// ---------------- LSTM elementwise steps ----------------
__global__ void lstm_step1()
{
    int idx = blockIdx.x * blockDim.x + threadIdx.x;
    int b = idx >> 8, e = idx & 255;
    const float* zq = g_zq + (size_t)b * 1024;
    float zi = zq[e], zg = zq[512 + e], zo = zq[768 + e];
    float c = sigm(zi) * tanhf(zg);
    g_c[idx] = c;
    g_h[idx] = g_se[idx] + sigm(zo) * tanhf(c);
}

__global__ void lstm_step()
{
    int idx = blockIdx.x * blockDim.x + threadIdx.x;
    int b = idx >> 8, e = idx & 255;
    const float* z = g_z + (size_t)b * 1024;
    float zi = z[e], zf = z[256 + e], zg = z[512 + e], zo = z[768 + e];
    float c = sigm(zf) * g_c[idx] + sigm(zi) * tanhf(zg);
    g_c[idx] = c;
    g_h[idx] = g_se[idx] + sigm(zo) * tanhf(c);
}

// ---------------- K13: normalized cosine output ----------------
__global__ void final_kernel(float* __restrict__ out)
{
    __shared__ float sm[8];
    int b = blockIdx.x, t = threadIdx.x;
    float hv = g_h[(size_t)b * D + t];
    float sv = g_sg[t];
    float dot = blk_reduce256(hv * sv, sm);
    float hh  = blk_reduce256(hv * hv, sm);
    float ss  = blk_reduce256(sv * sv, sm);
    if (t == 0)
        out[b] = dot / (fmaxf(sqrtf(hh), 1e-12f) * fmaxf(sqrtf(ss), 1e-12f));
}

// ---------------- launch ----------------
extern "C" void kernel_launch(void* const* d_in, const int* in_sizes, int n_in,
                              void* d_out, int out_size)
{
    const float* emb    = (const float*)d_in[0];
    const float* gcn_W  = (const float*)d_in[1];
    const float* gcn_wb = (const float*)d_in[2];
    const float* gate_W = (const float*)d_in[3];
    const float* gate_b = (const float*)d_in[4];
    const float* se_w1  = (const float*)d_in[5];
    const float* se_b1  = (const float*)d_in[6];
    const float* se_w2  = (const float*)d_in[7];
    const float* se_b2  = (const float*)d_in[8];
    const float* ln_g   = (const float*)d_in[9];
    const float* ln_b   = (const float*)d_in[10];
    const float* W_ih   = (const float*)d_in[11];
    const float* W_hh   = (const float*)d_in[12];
    const float* b_ih   = (const float*)d_in[13];
    const float* b_hh   = (const float*)d_in[14];
    const int*   query  = (const int*)d_in[15];
    const int*   support= (const int*)d_in[16];
    const int*   qlc    = (const int*)d_in[17];
    const int*   qrc    = (const int*)d_in[19];
    const int*   slc    = (const int*)d_in[21];
    const int*   src    = (const int*)d_in[23];
    const int*   knn    = (const int*)d_in[25];
    float* out = (float*)d_out;

    float *Agcn, *gcn, *X, *T, *Y, *se, *h, *Wih, *Whh, *bz, *zs, *zq, *z;
    cudaGetSymbolAddress((void**)&Agcn, g_Agcn);
    cudaGetSymbolAddress((void**)&gcn,  g_gcn);
    cudaGetSymbolAddress((void**)&X,    g_X);
    cudaGetSymbolAddress((void**)&T,    g_T);
    cudaGetSymbolAddress((void**)&Y,    g_Y);
    cudaGetSymbolAddress((void**)&se,   g_se);
    cudaGetSymbolAddress((void**)&h,    g_h);
    cudaGetSymbolAddress((void**)&Wih,  g_Wih);
    cudaGetSymbolAddress((void**)&Whh,  g_Whh);
    cudaGetSymbolAddress((void**)&bz,   g_bz);
    cudaGetSymbolAddress((void**)&zs,   g_zs);
    cudaGetSymbolAddress((void**)&zq,   g_zq);
    cudaGetSymbolAddress((void**)&z,    g_z);

    // K1: neighbor gather / top-k / means
    nbr_kernel<<<NR, 256>>>(emb, query, support, qlc, qrc, slc, src, knn);

    // K2: gcn GEMM  [8212,256] @ [128,256]^T -> tanh
    {
        dim3 grid(E / 64, (MG + 127) / 128);
        gemm_kernel<2,128><<<grid, 256>>>(Agcn, gcn_W, gcn_wb, nullptr, gcn, MG, E, D);
    }

    // K3: gate + concat
    gate_kernel<<<NR, 256>>>(gate_W, gate_b);

    // K4: se layer 1  [2053,256] @ [512,256]^T -> relu
    {
        dim3 grid(H / 64, (BQ + BS + 127) / 128);
        gemm_kernel<1,128><<<grid, 256>>>(X, se_w1, se_b1, nullptr, T, BQ + BS, H, D);
    }
    // K5: se layer 2  [2053,512] @ [256,512]^T + b2 + X   (BM=64 to fill the chip)
    {
        dim3 grid(D / 64, (BQ + BS + 63) / 64);
        gemm_kernel<0,64><<<grid, 256>>>(T, se_w2, se_b2, X, Y, BQ + BS, D, H);
    }
    // K6: layernorm
    ln_kernel<<<BQ + BS, 256>>>(ln_g, ln_b);
    // K7: support_g
    sg_kernel<<<1, 256>>>();
    // K8: pack LSTM weights + zs/bz
    pack_kernel<<<1024, 256>>>(W_ih, W_hh, b_ih, b_hh);

    // K9: zq = query_g @ Wih_p^T + bz   [2048,1024]
    {
        dim3 grid(1024 / 64, BQ / 128);
        gemm_kernel<0,128><<<grid, 256>>>(se, Wih, bz, nullptr, zq, BQ, 1024, D);
    }
    // step 1 (h_r = 0)
    lstm_step1<<<(BQ * D) / 256, 256>>>();
    // steps 2..4: z = zq + zs + h @ Whh_p^T
    for (int s = 1; s < STEPS; s++) {
        dim3 grid(1024 / 64, BQ / 128);
        gemm_kernel<0,128><<<grid, 256>>>(h, Whh, zs, zq, z, BQ, 1024, D);
        lstm_step<<<(BQ * D) / 256, 256>>>();
    }

    // K13: cosine similarity output
    final_kernel<<<BQ, 256>>>(out);
}

// round 5
// speedup vs baseline: 1.3198x; 1.1360x over previous
#include <cuda_runtime.h>
#include <cuda_bf16.h>
#include <math.h>
#include <stdint.h>

// ---------------- problem constants ----------------
#define V      200000
#define E      128
#define PAD    (V-1)
#define KNN_K  32
#define BQ     2048
#define BS     5
#define NN     128
#define KT     64
#define D      256
#define STEPS  4
#define H      512
#define NR     (2*BQ + 2*BS)   // 4106
#define MG     (2*NR)          // 8212

// ---------------- fp32 scratch ----------------
__device__ float g_Agcn[(size_t)MG * D];
__device__ float g_gcn[(size_t)MG * E];
__device__ float g_X[(size_t)(BQ + BS) * D];
__device__ float g_T[(size_t)(BQ + BS) * H];
__device__ float g_Y[(size_t)(BQ + BS) * D];
__device__ float g_se[(size_t)(BQ + BS) * D];
__device__ float g_sg[D];
__device__ float g_Wih[(size_t)1024 * D];
__device__ float g_Whh[(size_t)1024 * D];
__device__ float g_bz[1024];
__device__ float g_zs[1024];
__device__ float g_zq[(size_t)BQ * 1024];
__device__ float g_z[(size_t)BQ * 1024];
__device__ float g_c[(size_t)BQ * D];
__device__ float g_h[(size_t)BQ * D];

// ---------------- bf16 hi/lo packed operands (K' = 3K) ----------------
__device__ __nv_bfloat16 g_Agcnp[(size_t)MG * 3 * D];
__device__ __nv_bfloat16 g_gWp  [(size_t)E * 3 * D];
__device__ __nv_bfloat16 g_Xp   [(size_t)(BQ + BS) * 3 * D];
__device__ __nv_bfloat16 g_w1p  [(size_t)H * 3 * D];
__device__ __nv_bfloat16 g_Tp   [(size_t)(BQ + BS) * 3 * H];
__device__ __nv_bfloat16 g_w2p  [(size_t)D * 3 * H];
__device__ __nv_bfloat16 g_Wihp [(size_t)1024 * 3 * D];
__device__ __nv_bfloat16 g_Whhp [(size_t)1024 * 3 * D];
__device__ __nv_bfloat16 g_sep  [(size_t)BQ * 3 * D];
__device__ __nv_bfloat16 g_hp   [(size_t)BQ * 3 * D];

__device__ __forceinline__ float sigm(float x) { return 1.f / (1.f + __expf(-x)); }

__device__ __forceinline__ float blk_reduce256(float v, float* sm) {
    int t = threadIdx.x;
#pragma unroll
    for (int o = 16; o; o >>= 1) v += __shfl_xor_sync(0xffffffffu, v, o);
    if ((t & 31) == 0) sm[t >> 5] = v;
    __syncthreads();
    if (t < 32) {
        float r = (t < 8) ? sm[t] : 0.f;
#pragma unroll
        for (int o = 4; o; o >>= 1) r += __shfl_xor_sync(0xffffffffu, r, o);
        if (t == 0) sm[0] = r;
    }
    __syncthreads();
    float r = sm[0];
    __syncthreads();
    return r;
}

// ---------------- pack kernels: fp32 -> bf16 hi/lo, K' = 3K ----------------
__global__ void packA_kernel(const float* __restrict__ in, __nv_bfloat16* __restrict__ out, int K)
{
    int r = blockIdx.x, t = threadIdx.x;
    const float* s = in + (size_t)r * K;
    __nv_bfloat16* d = out + (size_t)r * 3 * K;
    for (int k = t; k < K; k += blockDim.x) {
        float x = s[k];
        __nv_bfloat16 hi = __float2bfloat16(x);
        __nv_bfloat16 lo = __float2bfloat16(x - __bfloat162float(hi));
        d[k] = hi; d[K + k] = lo; d[2 * K + k] = hi;   // [hi | lo | hi]
    }
}
__global__ void packB_kernel(const float* __restrict__ in, __nv_bfloat16* __restrict__ out, int K)
{
    int r = blockIdx.x, t = threadIdx.x;
    const float* s = in + (size_t)r * K;
    __nv_bfloat16* d = out + (size_t)r * 3 * K;
    for (int k = t; k < K; k += blockDim.x) {
        float x = s[k];
        __nv_bfloat16 hi = __float2bfloat16(x);
        __nv_bfloat16 lo = __float2bfloat16(x - __bfloat162float(hi));
        d[k] = hi; d[K + k] = hi; d[2 * K + k] = lo;   // [hi | hi | lo]
    }
}

// ---------------- HMMA (mma.sync bf16) GEMM ----------------
// C[M,N] = act(Ap[M,Kp] @ Bp[N,Kp]^T + bias [+ res])
// BM in {128,64}, BN=64, BK=64. 256 threads = 8 warps.
// BM=128: warps 4(M)x2(N), warp tile 32x32 (MI=2, NI=4)
// BM=64 : warps 2(M)x4(N), warp tile 32x16 (MI=2, NI=2)
// Kp % 64 == 0, N % 64 == 0.

__device__ __forceinline__ void mma16816(float* d, uint32_t a0, uint32_t a1, uint32_t a2, uint32_t a3,
                                         uint32_t b0, uint32_t b1)
{
    asm volatile(
        "mma.sync.aligned.m16n8k16.row.col.f32.bf16.bf16.f32 "
        "{%0,%1,%2,%3}, {%4,%5,%6,%7}, {%8,%9}, {%0,%1,%2,%3};"
        : "+f"(d[0]), "+f"(d[1]), "+f"(d[2]), "+f"(d[3])
        : "r"(a0), "r"(a1), "r"(a2), "r"(a3), "r"(b0), "r"(b1));
}

template<int ACT, int BM>
__global__ __launch_bounds__(256)
void hmma_gemm(const __nv_bfloat16* __restrict__ Ap, const __nv_bfloat16* __restrict__ Bp,
               const float* __restrict__ bias, const float* __restrict__ res,
               float* __restrict__ C, int M, int N, int Kp)
{
    constexpr int BN = 64, BK = 64, LDS_ = 72;         // smem row stride (bf16)
    constexpr int WARPS_N = (BM == 128) ? 2 : 4;
    constexpr int MI = 2;                               // 2 x m16 per warp (warp M = 32)
    constexpr int NI = BN / (WARPS_N * 8);              // 4 or 2 n8 tiles per warp
    constexpr int AIT = BM * 8 / 256;                   // uint4 A-loads per thread (4 or 2)

    extern __shared__ __align__(16) char dsm[];
    __nv_bfloat16* Asm = (__nv_bfloat16*)dsm;                       // [2][BM*LDS_]
    __nv_bfloat16* Bsm = (__nv_bfloat16*)(dsm + 2 * BM * LDS_ * 2); // [2][BN*LDS_]

    const int tid = threadIdx.x, lane = tid & 31, wid = tid >> 5;
    const int wm = wid / WARPS_N, wn = wid % WARPS_N;
    const int grp = lane >> 2, thr = lane & 3;
    const int m0 = blockIdx.y * BM, n0 = blockIdx.x * BN;

    float acc[MI][NI][4];
#pragma unroll
    for (int i = 0; i < MI; i++)
#pragma unroll
        for (int j = 0; j < NI; j++)
#pragma unroll
            for (int q = 0; q < 4; q++) acc[i][j][q] = 0.f;

    uint4 ra[AIT], rb[2];
    const int nchunks = Kp >> 6;

    // ---- load helpers (manually inlined pattern) ----
#define LOAD_REGS(c)                                                            \
    {                                                                           \
        _Pragma("unroll")                                                       \
        for (int i = 0; i < AIT; i++) {                                         \
            int u = tid + i * 256; int row = u >> 3, seg = u & 7;               \
            int gr = m0 + row; if (gr >= M) gr = M - 1;                         \
            ra[i] = *(const uint4*)(Ap + (size_t)gr * Kp + (size_t)(c) * 64 + seg * 8); \
        }                                                                       \
        _Pragma("unroll")                                                       \
        for (int i = 0; i < 2; i++) {                                           \
            int u = tid + i * 256; int row = u >> 3, seg = u & 7;               \
            rb[i] = *(const uint4*)(Bp + (size_t)(n0 + row) * Kp + (size_t)(c) * 64 + seg * 8); \
        }                                                                       \
    }
#define STORE_REGS(buf)                                                         \
    {                                                                           \
        _Pragma("unroll")                                                       \
        for (int i = 0; i < AIT; i++) {                                         \
            int u = tid + i * 256; int row = u >> 3, seg = u & 7;               \
            *(uint4*)(Asm + (size_t)(buf) * BM * LDS_ + row * LDS_ + seg * 8) = ra[i]; \
        }                                                                       \
        _Pragma("unroll")                                                       \
        for (int i = 0; i < 2; i++) {                                           \
            int u = tid + i * 256; int row = u >> 3, seg = u & 7;               \
            *(uint4*)(Bsm + (size_t)(buf) * BN * LDS_ + row * LDS_ + seg * 8) = rb[i]; \
        }                                                                       \
    }
#define COMPUTE(buf)                                                            \
    {                                                                           \
        const __nv_bfloat16* A_ = Asm + (size_t)(buf) * BM * LDS_;              \
        const __nv_bfloat16* B_ = Bsm + (size_t)(buf) * BN * LDS_;              \
        _Pragma("unroll")                                                       \
        for (int kk = 0; kk < 4; kk++) {                                        \
            int k0 = kk * 16;                                                   \
            uint32_t af[MI][4];                                                 \
            _Pragma("unroll")                                                   \
            for (int mi = 0; mi < MI; mi++) {                                   \
                int r = wm * 32 + mi * 16 + grp;                                \
                af[mi][0] = *(const uint32_t*)(A_ + r * LDS_ + k0 + thr * 2);   \
                af[mi][1] = *(const uint32_t*)(A_ + (r + 8) * LDS_ + k0 + thr * 2); \
                af[mi][2] = *(const uint32_t*)(A_ + r * LDS_ + k0 + 8 + thr * 2);   \
                af[mi][3] = *(const uint32_t*)(A_ + (r + 8) * LDS_ + k0 + 8 + thr * 2); \
            }                                                                   \
            _Pragma("unroll")                                                   \
            for (int ni = 0; ni < NI; ni++) {                                   \
                int cN = wn * (NI * 8) + ni * 8 + grp;                          \
                uint32_t b0 = *(const uint32_t*)(B_ + cN * LDS_ + k0 + thr * 2);    \
                uint32_t b1 = *(const uint32_t*)(B_ + cN * LDS_ + k0 + 8 + thr * 2);\
                _Pragma("unroll")                                               \
                for (int mi = 0; mi < MI; mi++)                                 \
                    mma16816(acc[mi][ni], af[mi][0], af[mi][1], af[mi][2], af[mi][3], b0, b1); \
            }                                                                   \
        }                                                                       \
    }

    // prologue
    LOAD_REGS(0);
    STORE_REGS(0);
    __syncthreads();

    int cur = 0;
    for (int c = 1; c < nchunks; c++) {
        LOAD_REGS(c);          // global prefetch overlaps compute below
        COMPUTE(cur);
        STORE_REGS(cur ^ 1);
        __syncthreads();
        cur ^= 1;
    }
    COMPUTE(cur);

    // epilogue: each thread owns 2 consecutive columns per (mi, ni, half)
#pragma unroll
    for (int mi = 0; mi < MI; mi++) {
#pragma unroll
        for (int ni = 0; ni < NI; ni++) {
            int col = n0 + wn * (NI * 8) + ni * 8 + thr * 2;
            float2 bb = *(const float2*)(bias + col);
#pragma unroll
            for (int half = 0; half < 2; half++) {
                int row = m0 + wm * 32 + mi * 16 + grp + half * 8;
                if (row >= M) continue;
                float v0 = acc[mi][ni][half * 2 + 0] + bb.x;
                float v1 = acc[mi][ni][half * 2 + 1] + bb.y;
                if (res) {
                    float2 rr = *(const float2*)(res + (size_t)row * N + col);
                    v0 += rr.x; v1 += rr.y;
                }
                if (ACT == 1) { v0 = fmaxf(v0, 0.f); v1 = fmaxf(v1, 0.f); }
                if (ACT == 2) { v0 = tanhf(v0); v1 = tanhf(v1); }
                float2 o; o.x = v0; o.y = v1;
                *(float2*)(C + (size_t)row * N + col) = o;
            }
        }
    }
#undef LOAD_REGS
#undef STORE_REGS
#undef COMPUTE
}

// ---------------- K1: neighbor encoder gather/top-k/mean ----------------
__global__ void nbr_kernel(const float* __restrict__ emb,
                           const int* __restrict__ query,
                           const int* __restrict__ support,
                           const int* __restrict__ qlc,
                           const int* __restrict__ qrc,
                           const int* __restrict__ slc,
                           const int* __restrict__ src,
                           const int* __restrict__ knn)
{
    int r = blockIdx.x;
    int tid = threadIdx.x, lane = tid & 31, warp = tid >> 5;

    const int* conn; int eid;
    if (r < BQ)               { eid = query[2*r];                 conn = qlc + (size_t)r*NN*2; }
    else if (r < 2*BQ)        { int b=r-BQ;   eid = query[2*b+1]; conn = qrc + (size_t)b*NN*2; }
    else if (r < 2*BQ+BS)     { int b=r-2*BQ; eid = support[2*b]; conn = slc + (size_t)b*NN*2; }
    else                      { int b=r-2*BQ-BS; eid = support[2*b+1]; conn = src + (size_t)b*NN*2; }
    if (eid < 0 || eid >= V) eid = PAD;

    __shared__ __align__(16) float cs[E];
    __shared__ float sims[NN];
    __shared__ float sumE[E], sumR[E], sumK[E];
    __shared__ int idsR[NN], idsE[NN], kid[KT], sel[KNN_K];
    __shared__ int selcnt;
    __shared__ float s_cn;

    if (tid < E) { cs[tid] = emb[(size_t)eid*E + tid]; sumE[tid]=0.f; sumR[tid]=0.f; sumK[tid]=0.f; }
    if (tid < NN) {
        int a = conn[2*tid], b = conn[2*tid+1];
        idsR[tid] = min(max(a,0), V-1);
        idsE[tid] = min(max(b,0), V-1);
    }
    if (tid < KT) { int kk = knn[(size_t)eid*KT + tid]; if (kk < 0 || kk >= V) kk = PAD; kid[tid] = kk; }
    if (tid == 0) selcnt = 0;
    __syncthreads();

    if (warp == 0) {
        float4 c = ((const float4*)cs)[lane];
        float s = c.x*c.x + c.y*c.y + c.z*c.z + c.w*c.w;
#pragma unroll
        for (int o = 16; o; o >>= 1) s += __shfl_xor_sync(0xffffffffu, s, o);
        if (lane == 0) s_cn = fmaxf(sqrtf(s), 1e-8f);
    }
    __syncthreads();
    float cn = s_cn;
    float4 c4 = ((const float4*)cs)[lane];

    for (int n = warp; n < NN; n += 8) {
        const float4* e4 = (const float4*)(emb + (size_t)idsE[n]*E);
        float4 v = e4[lane];
        float dd = v.x*c4.x + v.y*c4.y + v.z*c4.z + v.w*c4.w;
        float qq = v.x*v.x + v.y*v.y + v.z*v.z + v.w*v.w;
#pragma unroll
        for (int o = 16; o; o >>= 1) { dd += __shfl_xor_sync(0xffffffffu, dd, o);
                                       qq += __shfl_xor_sync(0xffffffffu, qq, o); }
        if (lane == 0) sims[n] = dd / (cn * fmaxf(sqrtf(qq), 1e-8f));
    }
    __syncthreads();

    if (tid < NN) {
        float sn = sims[tid]; int cnt = 0;
#pragma unroll 4
        for (int m = 0; m < NN; m++) {
            float sm = sims[m];
            cnt += (sm > sn) || (sm == sn && m < tid);
        }
        if (cnt < KNN_K) { int p = atomicAdd(&selcnt, 1); sel[p] = tid; }
    }
    __syncthreads();

    {
        float4 aE = make_float4(0,0,0,0), aR = make_float4(0,0,0,0);
        for (int p = warp; p < KNN_K; p += 8) {
            int n = sel[p];
            float4 v = ((const float4*)(emb + (size_t)idsE[n]*E))[lane];
            float4 w = ((const float4*)(emb + (size_t)idsR[n]*E))[lane];
            aE.x += v.x; aE.y += v.y; aE.z += v.z; aE.w += v.w;
            aR.x += w.x; aR.y += w.y; aR.z += w.z; aR.w += w.w;
        }
        atomicAdd(&sumE[lane*4+0], aE.x); atomicAdd(&sumE[lane*4+1], aE.y);
        atomicAdd(&sumE[lane*4+2], aE.z); atomicAdd(&sumE[lane*4+3], aE.w);
        atomicAdd(&sumR[lane*4+0], aR.x); atomicAdd(&sumR[lane*4+1], aR.y);
        atomicAdd(&sumR[lane*4+2], aR.z); atomicAdd(&sumR[lane*4+3], aR.w);
    }
    __syncthreads();
    if (tid == 0) selcnt = 0;

    for (int n = warp; n < KT; n += 8) {
        const float4* e4 = (const float4*)(emb + (size_t)kid[n]*E);
        float4 v = e4[lane];
        float dd = v.x*c4.x + v.y*c4.y + v.z*c4.z + v.w*c4.w;
        float qq = v.x*v.x + v.y*v.y + v.z*v.z + v.w*v.w;
#pragma unroll
        for (int o = 16; o; o >>= 1) { dd += __shfl_xor_sync(0xffffffffu, dd, o);
                                       qq += __shfl_xor_sync(0xffffffffu, qq, o); }
        if (lane == 0) sims[n] = dd / (cn * fmaxf(sqrtf(qq), 1e-8f));
    }
    __syncthreads();

    if (tid < KT) {
        float sn = sims[tid]; int cnt = 0;
#pragma unroll 4
        for (int m = 0; m < KT; m++) {
            float sm = sims[m];
            cnt += (sm > sn) || (sm == sn && m < tid);
        }
        if (cnt < KNN_K) { int p = atomicAdd(&selcnt, 1); sel[p] = tid; }
    }
    __syncthreads();

    {
        float4 aK = make_float4(0,0,0,0);
        for (int p = warp; p < KNN_K; p += 8) {
            int n = sel[p];
            float4 v = ((const float4*)(emb + (size_t)kid[n]*E))[lane];
            aK.x += v.x; aK.y += v.y; aK.z += v.z; aK.w += v.w;
        }
        atomicAdd(&sumK[lane*4+0], aK.x); atomicAdd(&sumK[lane*4+1], aK.y);
        atomicAdd(&sumK[lane*4+2], aK.z); atomicAdd(&sumK[lane*4+3], aK.w);
    }
    __syncthreads();

    if (tid < E) {
        const float inv = 1.f / (float)KNN_K;
        size_t o1 = (size_t)r * D;
        g_Agcn[o1 + tid]       = sumR[tid] * inv;
        g_Agcn[o1 + E + tid]   = sumE[tid] * inv;
        size_t o2 = (size_t)(NR + r) * D;
        g_Agcn[o2 + tid]       = 0.f;               // pad_rel == emb[PAD] == 0
        g_Agcn[o2 + E + tid]   = sumK[tid] * inv;
    }
}

// ---------------- K3: sigmoid gate + concat into X ----------------
__global__ void gate_kernel(const float* __restrict__ gate_W, const float* __restrict__ gate_b)
{
    __shared__ float sm[8];
    int r = blockIdx.x, t = threadIdx.x;
    float s = 0.f, k = 0.f, part = 0.f;
    if (t < E) {
        s = g_gcn[(size_t)r * E + t];
        k = g_gcn[(size_t)(NR + r) * E + t];
        part = s * gate_W[t] + k * gate_W[E + t];
    }
    float ain = blk_reduce256(part, sm);
    float a = sigm(ain + gate_b[0]);
    if (t < E) {
        float f = (1.f - a) * s + a * k;
        size_t dst;
        if (r < BQ)            dst = (size_t)r * D + t;
        else if (r < 2*BQ)     dst = (size_t)(r - BQ) * D + E + t;
        else if (r < 2*BQ+BS)  dst = (size_t)(BQ + r - 2*BQ) * D + t;
        else                   dst = (size_t)(BQ + r - 2*BQ - BS) * D + E + t;
        g_X[dst] = f;
    }
}

// ---------------- K6: layernorm ----------------
__global__ void ln_kernel(const float* __restrict__ ln_g, const float* __restrict__ ln_b)
{
    __shared__ float sm[8];
    int r = blockIdx.x, t = threadIdx.x;
    float x = g_Y[(size_t)r * D + t];
    float mu = blk_reduce256(x, sm) * (1.f / D);
    float d = x - mu;
    float var = blk_reduce256(d * d, sm) * (1.f / D);
    g_se[(size_t)r * D + t] = d * rsqrtf(var + 1e-5f) * ln_g[t] + ln_b[t];
}

// ---------------- K7: support_g ----------------
__global__ void sg_kernel()
{
    int t = threadIdx.x;
    float s = 0.f;
#pragma unroll
    for (int i = 0; i < BS; i++) s += g_se[(size_t)(BQ + i) * D + t];
    g_sg[t] = s * (1.f / BS);
}

// ---------------- K8: pack LSTM weights (fp32) + zs, bz ----------------
__global__ void pack_kernel(const float* __restrict__ W_ih, const float* __restrict__ W_hh,
                            const float* __restrict__ b_ih, const float* __restrict__ b_hh)
{
    __shared__ float sm[8];
    int p = blockIdx.x;
    int t = threadIdx.x;
    int blk = p >> 8, e = p & 255;
    int orig = blk * 512 + e;
    g_Wih[(size_t)p * D + t] = W_ih[(size_t)orig * D + t];
    g_Whh[(size_t)p * D + t] = W_hh[(size_t)orig * H + t];
    float part = W_hh[(size_t)orig * H + D + t] * g_sg[t];
    float zsv = blk_reduce256(part, sm);
    if (t == 0) {
        g_zs[p] = zsv;
        g_bz[p] = b_ih[orig] + b_hh[orig];
    }
}

// ---------------- LSTM elementwise ----------------
__global__ void lstm_step1()
{
    int idx = blockIdx.x * blockDim.x + threadIdx.x;
    int b = idx >> 8, e = idx & 255;
    const float* zq = g_zq + (size_t)b * 1024;
    float zi = zq[e], zg = zq[512 + e], zo = zq[768 + e];
    float c = sigm(zi) * tanhf(zg);
    g_c[idx] = c;
    g_h[idx] = g_se[idx] + sigm(zo) * tanhf(c);
}

__global__ void lstm_step()
{
    int idx = blockIdx.x * blockDim.x + threadIdx.x;
    int b = idx >> 8, e = idx & 255;
    const float* z = g_z + (size_t)b * 1024;
    float zi = z[e], zf = z[256 + e], zg = z[512 + e], zo = z[768 + e];
    float c = sigm(zf) * g_c[idx] + sigm(zi) * tanhf(zg);
    g_c[idx] = c;
    g_h[idx] = g_se[idx] + sigm(zo) * tanhf(c);
}

// ---------------- K13: cosine output ----------------
__global__ void final_kernel(float* __restrict__ out)
{
    __shared__ float sm[8];
    int b = blockIdx.x, t = threadIdx.x;
    float hv = g_h[(size_t)b * D + t];
    float sv = g_sg[t];
    float dot = blk_reduce256(hv * sv, sm);
    float hh  = blk_reduce256(hv * hv, sm);
    float ss  = blk_reduce256(sv * sv, sm);
    if (t == 0)
        out[b] = dot / (fmaxf(sqrtf(hh), 1e-12f) * fmaxf(sqrtf(ss), 1e-12f));
}

// ---------------- launch ----------------
#define SMEM_BM128 ((2 * 128 * 72 + 2 * 64 * 72) * 2)   // 55296
#define SMEM_BM64  ((2 * 64 * 72 + 2 * 64 * 72) * 2)    // 36864

extern "C" void kernel_launch(void* const* d_in, const int* in_sizes, int n_in,
                              void* d_out, int out_size)
{
    const float* emb    = (const float*)d_in[0];
    const float* gcn_W  = (const float*)d_in[1];
    const float* gcn_wb = (const float*)d_in[2];
    const float* gate_W = (const float*)d_in[3];
    const float* gate_b = (const float*)d_in[4];
    const float* se_w1  = (const float*)d_in[5];
    const float* se_b1  = (const float*)d_in[6];
    const float* se_w2  = (const float*)d_in[7];
    const float* se_b2  = (const float*)d_in[8];
    const float* ln_g   = (const float*)d_in[9];
    const float* ln_b   = (const float*)d_in[10];
    const float* W_ih   = (const float*)d_in[11];
    const float* W_hh   = (const float*)d_in[12];
    const float* b_ih   = (const float*)d_in[13];
    const float* b_hh   = (const float*)d_in[14];
    const int*   query  = (const int*)d_in[15];
    const int*   support= (const int*)d_in[16];
    const int*   qlc    = (const int*)d_in[17];
    const int*   qrc    = (const int*)d_in[19];
    const int*   slc    = (const int*)d_in[21];
    const int*   src    = (const int*)d_in[23];
    const int*   knn    = (const int*)d_in[25];
    float* out = (float*)d_out;

    float *Agcn, *gcn, *X, *T, *Y, *se, *h, *Wih, *Whh, *bz, *zs, *zq, *z;
    __nv_bfloat16 *Agcnp, *gWp, *Xp, *w1p, *Tp, *w2p, *Wihp, *Whhp, *sep, *hp;
    cudaGetSymbolAddress((void**)&Agcn, g_Agcn);
    cudaGetSymbolAddress((void**)&gcn,  g_gcn);
    cudaGetSymbolAddress((void**)&X,    g_X);
    cudaGetSymbolAddress((void**)&T,    g_T);
    cudaGetSymbolAddress((void**)&Y,    g_Y);
    cudaGetSymbolAddress((void**)&se,   g_se);
    cudaGetSymbolAddress((void**)&h,    g_h);
    cudaGetSymbolAddress((void**)&Wih,  g_Wih);
    cudaGetSymbolAddress((void**)&Whh,  g_Whh);
    cudaGetSymbolAddress((void**)&bz,   g_bz);
    cudaGetSymbolAddress((void**)&zs,   g_zs);
    cudaGetSymbolAddress((void**)&zq,   g_zq);
    cudaGetSymbolAddress((void**)&z,    g_z);
    cudaGetSymbolAddress((void**)&Agcnp, g_Agcnp);
    cudaGetSymbolAddress((void**)&gWp,   g_gWp);
    cudaGetSymbolAddress((void**)&Xp,    g_Xp);
    cudaGetSymbolAddress((void**)&w1p,   g_w1p);
    cudaGetSymbolAddress((void**)&Tp,    g_Tp);
    cudaGetSymbolAddress((void**)&w2p,   g_w2p);
    cudaGetSymbolAddress((void**)&Wihp,  g_Wihp);
    cudaGetSymbolAddress((void**)&Whhp,  g_Whhp);
    cudaGetSymbolAddress((void**)&sep,   g_sep);
    cudaGetSymbolAddress((void**)&hp,    g_hp);

    // opt-in > 48KB dynamic smem for the BM=128 variants (host-side, not a stream op)
    cudaFuncSetAttribute(hmma_gemm<2,128>, cudaFuncAttributeMaxDynamicSharedMemorySize, SMEM_BM128);
    cudaFuncSetAttribute(hmma_gemm<1,128>, cudaFuncAttributeMaxDynamicSharedMemorySize, SMEM_BM128);
    cudaFuncSetAttribute(hmma_gemm<0,128>, cudaFuncAttributeMaxDynamicSharedMemorySize, SMEM_BM128);

    // K1: neighbor gather / top-k / means
    nbr_kernel<<<NR, 256>>>(emb, query, support, qlc, qrc, slc, src, knn);

    // K2: gcn GEMM [8212,256]@[128,256]^T -> tanh (K'=768)
    packA_kernel<<<MG, 256>>>(Agcn, Agcnp, D);
    packB_kernel<<<E, 256>>>(gcn_W, gWp, D);
    hmma_gemm<2,128><<<dim3(E/64, (MG+127)/128), 256, SMEM_BM128>>>(Agcnp, gWp, gcn_wb, nullptr, gcn, MG, E, 3*D);

    // K3: gate + concat
    gate_kernel<<<NR, 256>>>(gate_W, gate_b);

    // K4: se layer 1 [2053,256]@[512,256]^T -> relu
    packA_kernel<<<BQ+BS, 256>>>(X, Xp, D);
    packB_kernel<<<H, 256>>>(se_w1, w1p, D);
    hmma_gemm<1,128><<<dim3(H/64, (BQ+BS+127)/128), 256, SMEM_BM128>>>(Xp, w1p, se_b1, nullptr, T, BQ+BS, H, 3*D);

    // K5: se layer 2 [2053,512]@[256,512]^T + b2 + X  (BM=64: fills chip, N small)
    packA_kernel<<<BQ+BS, 256>>>(T, Tp, H);
    packB_kernel<<<D, 256>>>(se_w2, w2p, H);
    hmma_gemm<0,64><<<dim3(D/64, (BQ+BS+63)/64), 256, SMEM_BM64>>>(Tp, w2p, se_b2, X, Y, BQ+BS, D, 3*H);

    // K6/K7/K8
    ln_kernel<<<BQ + BS, 256>>>(ln_g, ln_b);
    sg_kernel<<<1, 256>>>();
    pack_kernel<<<1024, 256>>>(W_ih, W_hh, b_ih, b_hh);
    packB_kernel<<<1024, 256>>>(Wih, Wihp, D);
    packB_kernel<<<1024, 256>>>(Whh, Whhp, D);

    // K9: zq = query_g @ Wih^T + bz  [2048,1024]
    packA_kernel<<<BQ, 256>>>(se, sep, D);
    hmma_gemm<0,128><<<dim3(1024/64, BQ/128), 256, SMEM_BM128>>>(sep, Wihp, bz, nullptr, zq, BQ, 1024, 3*D);

    lstm_step1<<<(BQ * D) / 256, 256>>>();
    for (int s = 1; s < STEPS; s++) {
        packA_kernel<<<BQ, 256>>>(h, hp, D);
        hmma_gemm<0,128><<<dim3(1024/64, BQ/128), 256, SMEM_BM128>>>(hp, Whhp, zs, zq, z, BQ, 1024, 3*D);
        lstm_step<<<(BQ * D) / 256, 256>>>();
    }

    final_kernel<<<BQ, 256>>>(out);
}

// round 6
// speedup vs baseline: 1.4138x; 1.0712x over previous
#include <cuda_runtime.h>
#include <cuda_bf16.h>
#include <math.h>
#include <stdint.h>

// ---------------- problem constants ----------------
#define V      200000
#define E      128
#define PAD    (V-1)
#define KNN_K  32
#define BQ     2048
#define BS     5
#define NN     128
#define KT     64
#define D      256
#define STEPS  4
#define H      512
#define NR     (2*BQ + 2*BS)   // 4106
#define MG     (2*NR)          // 8212

// ---------------- fp32 scratch ----------------
__device__ float g_gcn[(size_t)MG * E];
__device__ float g_X[(size_t)(BQ + BS) * D];    // residual for K5
__device__ float g_Y[(size_t)(BQ + BS) * D];
__device__ float g_se[(size_t)(BQ + BS) * D];
__device__ float g_sg[D];
__device__ float g_bz[1024];
__device__ float g_zs[1024];
__device__ float g_zq[(size_t)BQ * 1024];
__device__ float g_z[(size_t)BQ * 1024];
__device__ float g_c[(size_t)BQ * D];
__device__ float g_h[(size_t)BQ * D];

// ---------------- bf16 hi/lo packed operands (K' = 3K) ----------------
// A layout along K': [hi | lo | hi]; B layout: [hi | hi | lo]
__device__ __nv_bfloat16 g_Agcnp[(size_t)MG * 3 * D];
__device__ __nv_bfloat16 g_gWp  [(size_t)E * 3 * D];
__device__ __nv_bfloat16 g_Xp   [(size_t)(BQ + BS) * 3 * D];
__device__ __nv_bfloat16 g_w1p  [(size_t)H * 3 * D];
__device__ __nv_bfloat16 g_Tp   [(size_t)(BQ + BS) * 3 * H];
__device__ __nv_bfloat16 g_w2p  [(size_t)D * 3 * H];
__device__ __nv_bfloat16 g_Wihp [(size_t)1024 * 3 * D];
__device__ __nv_bfloat16 g_Whhp [(size_t)1024 * 3 * D];
__device__ __nv_bfloat16 g_sep  [(size_t)BQ * 3 * D];
__device__ __nv_bfloat16 g_hp   [(size_t)BQ * 3 * D];

__device__ __forceinline__ float sigm(float x) { return 1.f / (1.f + __expf(-x)); }

__device__ __forceinline__ void hilo(float x, __nv_bfloat16& hi, __nv_bfloat16& lo) {
    hi = __float2bfloat16(x);
    lo = __float2bfloat16(x - __bfloat162float(hi));
}

__device__ __forceinline__ float blk_reduce256(float v, float* sm) {
    int t = threadIdx.x;
#pragma unroll
    for (int o = 16; o; o >>= 1) v += __shfl_xor_sync(0xffffffffu, v, o);
    if ((t & 31) == 0) sm[t >> 5] = v;
    __syncthreads();
    if (t < 32) {
        float r = (t < 8) ? sm[t] : 0.f;
#pragma unroll
        for (int o = 4; o; o >>= 1) r += __shfl_xor_sync(0xffffffffu, r, o);
        if (t == 0) sm[0] = r;
    }
    __syncthreads();
    float r = sm[0];
    __syncthreads();
    return r;
}

// ---------------- weight pack (B layout): fp32 -> [hi|hi|lo] ----------------
__global__ void packB_kernel(const float* __restrict__ in, __nv_bfloat16* __restrict__ out, int K)
{
    int r = blockIdx.x, t = threadIdx.x;
    const float* s = in + (size_t)r * K;
    __nv_bfloat16* d = out + (size_t)r * 3 * K;
    for (int k = t; k < K; k += blockDim.x) {
        __nv_bfloat16 hi, lo; hilo(s[k], hi, lo);
        d[k] = hi; d[K + k] = hi; d[2 * K + k] = lo;
    }
}

// ---------------- HMMA (mma.sync bf16) GEMM ----------------
// C[M,N] = act(Ap[M,Kp] @ Bp[N,Kp]^T + bias [+ res])
// PACKOUT=0: write fp32 C.  PACKOUT=1: write bf16 A-layout packed Cp (stride 3N).
__device__ __forceinline__ void mma16816(float* d, uint32_t a0, uint32_t a1, uint32_t a2, uint32_t a3,
                                         uint32_t b0, uint32_t b1)
{
    asm volatile(
        "mma.sync.aligned.m16n8k16.row.col.f32.bf16.bf16.f32 "
        "{%0,%1,%2,%3}, {%4,%5,%6,%7}, {%8,%9}, {%0,%1,%2,%3};"
        : "+f"(d[0]), "+f"(d[1]), "+f"(d[2]), "+f"(d[3])
        : "r"(a0), "r"(a1), "r"(a2), "r"(a3), "r"(b0), "r"(b1));
}

template<int ACT, int BM, int PACKOUT>
__global__ __launch_bounds__(256)
void hmma_gemm(const __nv_bfloat16* __restrict__ Ap, const __nv_bfloat16* __restrict__ Bp,
               const float* __restrict__ bias, const float* __restrict__ res,
               float* __restrict__ C, __nv_bfloat16* __restrict__ Cp, int M, int N, int Kp)
{
    constexpr int BN = 64, LDS_ = 72;
    constexpr int WARPS_N = (BM == 128) ? 2 : 4;
    constexpr int MI = 2;
    constexpr int NI = BN / (WARPS_N * 8);
    constexpr int AIT = BM * 8 / 256;

    extern __shared__ __align__(16) char dsm[];
    __nv_bfloat16* Asm = (__nv_bfloat16*)dsm;
    __nv_bfloat16* Bsm = (__nv_bfloat16*)(dsm + 2 * BM * LDS_ * 2);

    const int tid = threadIdx.x, lane = tid & 31, wid = tid >> 5;
    const int wm = wid / WARPS_N, wn = wid % WARPS_N;
    const int grp = lane >> 2, thr = lane & 3;
    const int m0 = blockIdx.y * BM, n0 = blockIdx.x * BN;

    float acc[MI][NI][4];
#pragma unroll
    for (int i = 0; i < MI; i++)
#pragma unroll
        for (int j = 0; j < NI; j++)
#pragma unroll
            for (int q = 0; q < 4; q++) acc[i][j][q] = 0.f;

    uint4 ra[AIT], rb[2];
    const int nchunks = Kp >> 6;

#define LOAD_REGS(c)                                                            \
    {                                                                           \
        _Pragma("unroll")                                                       \
        for (int i = 0; i < AIT; i++) {                                         \
            int u = tid + i * 256; int row = u >> 3, seg = u & 7;               \
            int gr = m0 + row; if (gr >= M) gr = M - 1;                         \
            ra[i] = *(const uint4*)(Ap + (size_t)gr * Kp + (size_t)(c) * 64 + seg * 8); \
        }                                                                       \
        _Pragma("unroll")                                                       \
        for (int i = 0; i < 2; i++) {                                           \
            int u = tid + i * 256; int row = u >> 3, seg = u & 7;               \
            rb[i] = *(const uint4*)(Bp + (size_t)(n0 + row) * Kp + (size_t)(c) * 64 + seg * 8); \
        }                                                                       \
    }
#define STORE_REGS(buf)                                                         \
    {                                                                           \
        _Pragma("unroll")                                                       \
        for (int i = 0; i < AIT; i++) {                                         \
            int u = tid + i * 256; int row = u >> 3, seg = u & 7;               \
            *(uint4*)(Asm + (size_t)(buf) * BM * LDS_ + row * LDS_ + seg * 8) = ra[i]; \
        }                                                                       \
        _Pragma("unroll")                                                       \
        for (int i = 0; i < 2; i++) {                                           \
            int u = tid + i * 256; int row = u >> 3, seg = u & 7;               \
            *(uint4*)(Bsm + (size_t)(buf) * BN * LDS_ + row * LDS_ + seg * 8) = rb[i]; \
        }                                                                       \
    }
#define COMPUTE(buf)                                                            \
    {                                                                           \
        const __nv_bfloat16* A_ = Asm + (size_t)(buf) * BM * LDS_;              \
        const __nv_bfloat16* B_ = Bsm + (size_t)(buf) * BN * LDS_;              \
        _Pragma("unroll")                                                       \
        for (int kk = 0; kk < 4; kk++) {                                        \
            int k0 = kk * 16;                                                   \
            uint32_t af[MI][4];                                                 \
            _Pragma("unroll")                                                   \
            for (int mi = 0; mi < MI; mi++) {                                   \
                int r = wm * 32 + mi * 16 + grp;                                \
                af[mi][0] = *(const uint32_t*)(A_ + r * LDS_ + k0 + thr * 2);   \
                af[mi][1] = *(const uint32_t*)(A_ + (r + 8) * LDS_ + k0 + thr * 2); \
                af[mi][2] = *(const uint32_t*)(A_ + r * LDS_ + k0 + 8 + thr * 2);   \
                af[mi][3] = *(const uint32_t*)(A_ + (r + 8) * LDS_ + k0 + 8 + thr * 2); \
            }                                                                   \
            _Pragma("unroll")                                                   \
            for (int ni = 0; ni < NI; ni++) {                                   \
                int cN = wn * (NI * 8) + ni * 8 + grp;                          \
                uint32_t b0 = *(const uint32_t*)(B_ + cN * LDS_ + k0 + thr * 2);    \
                uint32_t b1 = *(const uint32_t*)(B_ + cN * LDS_ + k0 + 8 + thr * 2);\
                _Pragma("unroll")                                               \
                for (int mi = 0; mi < MI; mi++)                                 \
                    mma16816(acc[mi][ni], af[mi][0], af[mi][1], af[mi][2], af[mi][3], b0, b1); \
            }                                                                   \
        }                                                                       \
    }

    LOAD_REGS(0);
    STORE_REGS(0);
    __syncthreads();

    int cur = 0;
    for (int c = 1; c < nchunks; c++) {
        LOAD_REGS(c);
        COMPUTE(cur);
        STORE_REGS(cur ^ 1);
        __syncthreads();
        cur ^= 1;
    }
    COMPUTE(cur);

#pragma unroll
    for (int mi = 0; mi < MI; mi++) {
#pragma unroll
        for (int ni = 0; ni < NI; ni++) {
            int col = n0 + wn * (NI * 8) + ni * 8 + thr * 2;
            float2 bb = *(const float2*)(bias + col);
#pragma unroll
            for (int half = 0; half < 2; half++) {
                int row = m0 + wm * 32 + mi * 16 + grp + half * 8;
                if (row >= M) continue;
                float v0 = acc[mi][ni][half * 2 + 0] + bb.x;
                float v1 = acc[mi][ni][half * 2 + 1] + bb.y;
                if (res) {
                    float2 rr = *(const float2*)(res + (size_t)row * N + col);
                    v0 += rr.x; v1 += rr.y;
                }
                if (ACT == 1) { v0 = fmaxf(v0, 0.f); v1 = fmaxf(v1, 0.f); }
                if (ACT == 2) { v0 = tanhf(v0); v1 = tanhf(v1); }
                if (PACKOUT == 0) {
                    float2 o; o.x = v0; o.y = v1;
                    *(float2*)(C + (size_t)row * N + col) = o;
                } else {
                    __nv_bfloat16 h0, l0, h1, l1;
                    hilo(v0, h0, l0); hilo(v1, h1, l1);
                    __nv_bfloat16* dst = Cp + (size_t)row * 3 * N;
                    __nv_bfloat162 hh; hh.x = h0; hh.y = h1;
                    __nv_bfloat162 ll; ll.x = l0; ll.y = l1;
                    *(__nv_bfloat162*)(dst + col)         = hh;
                    *(__nv_bfloat162*)(dst + N + col)     = ll;
                    *(__nv_bfloat162*)(dst + 2 * N + col) = hh;
                }
            }
        }
    }
#undef LOAD_REGS
#undef STORE_REGS
#undef COMPUTE
}

// ---------------- K1: neighbor encoder gather/top-k/mean -> packed A rows ----------------
__global__ void nbr_kernel(const float* __restrict__ emb,
                           const int* __restrict__ query,
                           const int* __restrict__ support,
                           const int* __restrict__ qlc,
                           const int* __restrict__ qrc,
                           const int* __restrict__ slc,
                           const int* __restrict__ src,
                           const int* __restrict__ knn)
{
    int r = blockIdx.x;
    int tid = threadIdx.x, lane = tid & 31, warp = tid >> 5;

    const int* conn; int eid;
    if (r < BQ)               { eid = query[2*r];                 conn = qlc + (size_t)r*NN*2; }
    else if (r < 2*BQ)        { int b=r-BQ;   eid = query[2*b+1]; conn = qrc + (size_t)b*NN*2; }
    else if (r < 2*BQ+BS)     { int b=r-2*BQ; eid = support[2*b]; conn = slc + (size_t)b*NN*2; }
    else                      { int b=r-2*BQ-BS; eid = support[2*b+1]; conn = src + (size_t)b*NN*2; }
    if (eid < 0 || eid >= V) eid = PAD;

    __shared__ __align__(16) float cs[E];
    __shared__ float sims[NN];
    __shared__ float sumE[E], sumR[E], sumK[E];
    __shared__ int idsR[NN], idsE[NN], kid[KT], sel[KNN_K];
    __shared__ int selcnt;
    __shared__ float s_cn;

    if (tid < E) { cs[tid] = emb[(size_t)eid*E + tid]; sumE[tid]=0.f; sumR[tid]=0.f; sumK[tid]=0.f; }
    if (tid < NN) {
        int a = conn[2*tid], b = conn[2*tid+1];
        idsR[tid] = min(max(a,0), V-1);
        idsE[tid] = min(max(b,0), V-1);
    }
    if (tid < KT) { int kk = knn[(size_t)eid*KT + tid]; if (kk < 0 || kk >= V) kk = PAD; kid[tid] = kk; }
    if (tid == 0) selcnt = 0;
    __syncthreads();

    if (warp == 0) {
        float4 c = ((const float4*)cs)[lane];
        float s = c.x*c.x + c.y*c.y + c.z*c.z + c.w*c.w;
#pragma unroll
        for (int o = 16; o; o >>= 1) s += __shfl_xor_sync(0xffffffffu, s, o);
        if (lane == 0) s_cn = fmaxf(sqrtf(s), 1e-8f);
    }
    __syncthreads();
    float cn = s_cn;
    float4 c4 = ((const float4*)cs)[lane];

    for (int n = warp; n < NN; n += 8) {
        const float4* e4 = (const float4*)(emb + (size_t)idsE[n]*E);
        float4 v = e4[lane];
        float dd = v.x*c4.x + v.y*c4.y + v.z*c4.z + v.w*c4.w;
        float qq = v.x*v.x + v.y*v.y + v.z*v.z + v.w*v.w;
#pragma unroll
        for (int o = 16; o; o >>= 1) { dd += __shfl_xor_sync(0xffffffffu, dd, o);
                                       qq += __shfl_xor_sync(0xffffffffu, qq, o); }
        if (lane == 0) sims[n] = dd / (cn * fmaxf(sqrtf(qq), 1e-8f));
    }
    __syncthreads();

    if (tid < NN) {
        float sn = sims[tid]; int cnt = 0;
#pragma unroll 4
        for (int m = 0; m < NN; m++) {
            float sm = sims[m];
            cnt += (sm > sn) || (sm == sn && m < tid);
        }
        if (cnt < KNN_K) { int p = atomicAdd(&selcnt, 1); sel[p] = tid; }
    }
    __syncthreads();

    {
        float4 aE = make_float4(0,0,0,0), aR = make_float4(0,0,0,0);
        for (int p = warp; p < KNN_K; p += 8) {
            int n = sel[p];
            float4 v = ((const float4*)(emb + (size_t)idsE[n]*E))[lane];
            float4 w = ((const float4*)(emb + (size_t)idsR[n]*E))[lane];
            aE.x += v.x; aE.y += v.y; aE.z += v.z; aE.w += v.w;
            aR.x += w.x; aR.y += w.y; aR.z += w.z; aR.w += w.w;
        }
        atomicAdd(&sumE[lane*4+0], aE.x); atomicAdd(&sumE[lane*4+1], aE.y);
        atomicAdd(&sumE[lane*4+2], aE.z); atomicAdd(&sumE[lane*4+3], aE.w);
        atomicAdd(&sumR[lane*4+0], aR.x); atomicAdd(&sumR[lane*4+1], aR.y);
        atomicAdd(&sumR[lane*4+2], aR.z); atomicAdd(&sumR[lane*4+3], aR.w);
    }
    __syncthreads();
    if (tid == 0) selcnt = 0;

    for (int n = warp; n < KT; n += 8) {
        const float4* e4 = (const float4*)(emb + (size_t)kid[n]*E);
        float4 v = e4[lane];
        float dd = v.x*c4.x + v.y*c4.y + v.z*c4.z + v.w*c4.w;
        float qq = v.x*v.x + v.y*v.y + v.z*v.z + v.w*v.w;
#pragma unroll
        for (int o = 16; o; o >>= 1) { dd += __shfl_xor_sync(0xffffffffu, dd, o);
                                       qq += __shfl_xor_sync(0xffffffffu, qq, o); }
        if (lane == 0) sims[n] = dd / (cn * fmaxf(sqrtf(qq), 1e-8f));
    }
    __syncthreads();

    if (tid < KT) {
        float sn = sims[tid]; int cnt = 0;
#pragma unroll 4
        for (int m = 0; m < KT; m++) {
            float sm = sims[m];
            cnt += (sm > sn) || (sm == sn && m < tid);
        }
        if (cnt < KNN_K) { int p = atomicAdd(&selcnt, 1); sel[p] = tid; }
    }
    __syncthreads();

    {
        float4 aK = make_float4(0,0,0,0);
        for (int p = warp; p < KNN_K; p += 8) {
            int n = sel[p];
            float4 v = ((const float4*)(emb + (size_t)kid[n]*E))[lane];
            aK.x += v.x; aK.y += v.y; aK.z += v.z; aK.w += v.w;
        }
        atomicAdd(&sumK[lane*4+0], aK.x); atomicAdd(&sumK[lane*4+1], aK.y);
        atomicAdd(&sumK[lane*4+2], aK.z); atomicAdd(&sumK[lane*4+3], aK.w);
    }
    __syncthreads();

    if (tid < E) {
        const float inv = 1.f / (float)KNN_K;
        float vr = sumR[tid] * inv, ve = sumE[tid] * inv, vk = sumK[tid] * inv;
        __nv_bfloat16 hr, lr, he, le, hk, lk;
        hilo(vr, hr, lr); hilo(ve, he, le); hilo(vk, hk, lk);
        const __nv_bfloat16 z0 = __float2bfloat16(0.f);
        // structural row r: cat = [rel | ent], packed A layout [hi|lo|hi]
        size_t b1 = (size_t)r * 3 * D;
        g_Agcnp[b1 + tid]           = hr;  g_Agcnp[b1 + E + tid]           = he;
        g_Agcnp[b1 + D + tid]       = lr;  g_Agcnp[b1 + D + E + tid]       = le;
        g_Agcnp[b1 + 2*D + tid]     = hr;  g_Agcnp[b1 + 2*D + E + tid]     = he;
        // knn row NR+r: cat = [0 | knn]
        size_t b2 = (size_t)(NR + r) * 3 * D;
        g_Agcnp[b2 + tid]           = z0;  g_Agcnp[b2 + E + tid]           = hk;
        g_Agcnp[b2 + D + tid]       = z0;  g_Agcnp[b2 + D + E + tid]       = lk;
        g_Agcnp[b2 + 2*D + tid]     = z0;  g_Agcnp[b2 + 2*D + E + tid]     = hk;
    }
}

// ---------------- K3: sigmoid gate + concat -> X fp32 + Xp packed ----------------
__global__ void gate_kernel(const float* __restrict__ gate_W, const float* __restrict__ gate_b)
{
    __shared__ float sm[8];
    int r = blockIdx.x, t = threadIdx.x;
    float s = 0.f, k = 0.f, part = 0.f;
    if (t < E) {
        s = g_gcn[(size_t)r * E + t];
        k = g_gcn[(size_t)(NR + r) * E + t];
        part = s * gate_W[t] + k * gate_W[E + t];
    }
    float ain = blk_reduce256(part, sm);
    float a = sigm(ain + gate_b[0]);
    if (t < E) {
        float f = (1.f - a) * s + a * k;
        int row, col;
        if (r < BQ)            { row = r;              col = t; }
        else if (r < 2*BQ)     { row = r - BQ;         col = E + t; }
        else if (r < 2*BQ+BS)  { row = BQ + r - 2*BQ;  col = t; }
        else                   { row = BQ + r - 2*BQ - BS; col = E + t; }
        g_X[(size_t)row * D + col] = f;
        __nv_bfloat16 hi, lo; hilo(f, hi, lo);
        size_t b = (size_t)row * 3 * D;
        g_Xp[b + col] = hi; g_Xp[b + D + col] = lo; g_Xp[b + 2*D + col] = hi;
    }
}

// ---------------- K6: layernorm -> se fp32 + sep packed (query rows) ----------------
__global__ void ln_kernel(const float* __restrict__ ln_g, const float* __restrict__ ln_b)
{
    __shared__ float sm[8];
    int r = blockIdx.x, t = threadIdx.x;
    float x = g_Y[(size_t)r * D + t];
    float mu = blk_reduce256(x, sm) * (1.f / D);
    float d = x - mu;
    float var = blk_reduce256(d * d, sm) * (1.f / D);
    float v = d * rsqrtf(var + 1e-5f) * ln_g[t] + ln_b[t];
    g_se[(size_t)r * D + t] = v;
    if (r < BQ) {
        __nv_bfloat16 hi, lo; hilo(v, hi, lo);
        size_t b = (size_t)r * 3 * D;
        g_sep[b + t] = hi; g_sep[b + D + t] = lo; g_sep[b + 2*D + t] = hi;
    }
}

// ---------------- K7: support_g ----------------
__global__ void sg_kernel()
{
    int t = threadIdx.x;
    float s = 0.f;
#pragma unroll
    for (int i = 0; i < BS; i++) s += g_se[(size_t)(BQ + i) * D + t];
    g_sg[t] = s * (1.f / BS);
}

// ---------------- K8: pack LSTM weights -> packed B layout + zs, bz ----------------
__global__ void pack_kernel(const float* __restrict__ W_ih, const float* __restrict__ W_hh,
                            const float* __restrict__ b_ih, const float* __restrict__ b_hh)
{
    __shared__ float sm[8];
    int p = blockIdx.x;
    int t = threadIdx.x;
    int blk = p >> 8, e = p & 255;
    int orig = blk * 512 + e;
    float wih = W_ih[(size_t)orig * D + t];
    float whh = W_hh[(size_t)orig * H + t];
    {
        __nv_bfloat16 hi, lo; hilo(wih, hi, lo);
        size_t b = (size_t)p * 3 * D;
        g_Wihp[b + t] = hi; g_Wihp[b + D + t] = hi; g_Wihp[b + 2*D + t] = lo;
    }
    {
        __nv_bfloat16 hi, lo; hilo(whh, hi, lo);
        size_t b = (size_t)p * 3 * D;
        g_Whhp[b + t] = hi; g_Whhp[b + D + t] = hi; g_Whhp[b + 2*D + t] = lo;
    }
    float part = W_hh[(size_t)orig * H + D + t] * g_sg[t];
    float zsv = blk_reduce256(part, sm);
    if (t == 0) {
        g_zs[p] = zsv;
        g_bz[p] = b_ih[orig] + b_hh[orig];
    }
}

// ---------------- LSTM elementwise (write h fp32 + hp packed) ----------------
__global__ void lstm_step1()
{
    int idx = blockIdx.x * blockDim.x + threadIdx.x;
    int b = idx >> 8, e = idx & 255;
    const float* zq = g_zq + (size_t)b * 1024;
    float zi = zq[e], zg = zq[512 + e], zo = zq[768 + e];
    float c = sigm(zi) * tanhf(zg);
    g_c[idx] = c;
    float hv = g_se[idx] + sigm(zo) * tanhf(c);
    g_h[idx] = hv;
    __nv_bfloat16 hi, lo; hilo(hv, hi, lo);
    size_t base = (size_t)b * 3 * D;
    g_hp[base + e] = hi; g_hp[base + D + e] = lo; g_hp[base + 2*D + e] = hi;
}

__global__ void lstm_step()
{
    int idx = blockIdx.x * blockDim.x + threadIdx.x;
    int b = idx >> 8, e = idx & 255;
    const float* z = g_z + (size_t)b * 1024;
    float zi = z[e], zf = z[256 + e], zg = z[512 + e], zo = z[768 + e];
    float c = sigm(zf) * g_c[idx] + sigm(zi) * tanhf(zg);
    g_c[idx] = c;
    float hv = g_se[idx] + sigm(zo) * tanhf(c);
    g_h[idx] = hv;
    __nv_bfloat16 hi, lo; hilo(hv, hi, lo);
    size_t base = (size_t)b * 3 * D;
    g_hp[base + e] = hi; g_hp[base + D + e] = lo; g_hp[base + 2*D + e] = hi;
}

// ---------------- K13: cosine output ----------------
__global__ void final_kernel(float* __restrict__ out)
{
    __shared__ float sm[8];
    int b = blockIdx.x, t = threadIdx.x;
    float hv = g_h[(size_t)b * D + t];
    float sv = g_sg[t];
    float dot = blk_reduce256(hv * sv, sm);
    float hh  = blk_reduce256(hv * hv, sm);
    float ss  = blk_reduce256(sv * sv, sm);
    if (t == 0)
        out[b] = dot / (fmaxf(sqrtf(hh), 1e-12f) * fmaxf(sqrtf(ss), 1e-12f));
}

// ---------------- launch ----------------
#define SMEM_BM128 ((2 * 128 * 72 + 2 * 64 * 72) * 2)   // 55296
#define SMEM_BM64  ((2 * 64 * 72 + 2 * 64 * 72) * 2)    // 36864

extern "C" void kernel_launch(void* const* d_in, const int* in_sizes, int n_in,
                              void* d_out, int out_size)
{
    const float* emb    = (const float*)d_in[0];
    const float* gcn_W  = (const float*)d_in[1];
    const float* gcn_wb = (const float*)d_in[2];
    const float* gate_W = (const float*)d_in[3];
    const float* gate_b = (const float*)d_in[4];
    const float* se_w1  = (const float*)d_in[5];
    const float* se_b1  = (const float*)d_in[6];
    const float* se_w2  = (const float*)d_in[7];
    const float* se_b2  = (const float*)d_in[8];
    const float* ln_g   = (const float*)d_in[9];
    const float* ln_b   = (const float*)d_in[10];
    const float* W_ih   = (const float*)d_in[11];
    const float* W_hh   = (const float*)d_in[12];
    const float* b_ih   = (const float*)d_in[13];
    const float* b_hh   = (const float*)d_in[14];
    const int*   query  = (const int*)d_in[15];
    const int*   support= (const int*)d_in[16];
    const int*   qlc    = (const int*)d_in[17];
    const int*   qrc    = (const int*)d_in[19];
    const int*   slc    = (const int*)d_in[21];
    const int*   src    = (const int*)d_in[23];
    const int*   knn    = (const int*)d_in[25];
    float* out = (float*)d_out;

    float *gcn, *X, *Y, *se, *h, *bz, *zs, *zq, *z;
    __nv_bfloat16 *Agcnp, *gWp, *Xp, *w1p, *Tp, *w2p, *Wihp, *Whhp, *sep, *hp;
    cudaGetSymbolAddress((void**)&gcn,  g_gcn);
    cudaGetSymbolAddress((void**)&X,    g_X);
    cudaGetSymbolAddress((void**)&Y,    g_Y);
    cudaGetSymbolAddress((void**)&se,   g_se);
    cudaGetSymbolAddress((void**)&h,    g_h);
    cudaGetSymbolAddress((void**)&bz,   g_bz);
    cudaGetSymbolAddress((void**)&zs,   g_zs);
    cudaGetSymbolAddress((void**)&zq,   g_zq);
    cudaGetSymbolAddress((void**)&z,    g_z);
    cudaGetSymbolAddress((void**)&Agcnp, g_Agcnp);
    cudaGetSymbolAddress((void**)&gWp,   g_gWp);
    cudaGetSymbolAddress((void**)&Xp,    g_Xp);
    cudaGetSymbolAddress((void**)&w1p,   g_w1p);
    cudaGetSymbolAddress((void**)&Tp,    g_Tp);
    cudaGetSymbolAddress((void**)&w2p,   g_w2p);
    cudaGetSymbolAddress((void**)&Wihp,  g_Wihp);
    cudaGetSymbolAddress((void**)&Whhp,  g_Whhp);
    cudaGetSymbolAddress((void**)&sep,   g_sep);
    cudaGetSymbolAddress((void**)&hp,    g_hp);

    cudaFuncSetAttribute(hmma_gemm<0,128,0>, cudaFuncAttributeMaxDynamicSharedMemorySize, SMEM_BM128);

    // K1: neighbor gather / top-k / means -> packed A rows
    nbr_kernel<<<NR, 256>>>(emb, query, support, qlc, qrc, slc, src, knn);

    // K2: gcn GEMM [8212,256]@[128,256]^T -> tanh, fp32 out  (BM=64: 258 CTAs)
    packB_kernel<<<E, 256>>>(gcn_W, gWp, D);
    hmma_gemm<2,64,0><<<dim3(E/64, (MG+63)/64), 256, SMEM_BM64>>>(Agcnp, gWp, gcn_wb, nullptr, gcn, nullptr, MG, E, 3*D);

    // K3: gate + concat (writes X + Xp)
    gate_kernel<<<NR, 256>>>(gate_W, gate_b);

    // K4: se layer 1 [2053,256]@[512,256]^T -> relu, PACKED out Tp  (BM=64: 264 CTAs)
    packB_kernel<<<H, 256>>>(se_w1, w1p, D);
    hmma_gemm<1,64,1><<<dim3(H/64, (BQ+BS+63)/64), 256, SMEM_BM64>>>(Xp, w1p, se_b1, nullptr, nullptr, Tp, BQ+BS, H, 3*D);

    // K5: se layer 2 [2053,512]@[256,512]^T + b2 + X -> Y fp32
    packB_kernel<<<D, 256>>>(se_w2, w2p, H);
    hmma_gemm<0,64,0><<<dim3(D/64, (BQ+BS+63)/64), 256, SMEM_BM64>>>(Tp, w2p, se_b2, X, Y, nullptr, BQ+BS, D, 3*H);

    // K6/K7/K8
    ln_kernel<<<BQ + BS, 256>>>(ln_g, ln_b);
    sg_kernel<<<1, 256>>>();
    pack_kernel<<<1024, 256>>>(W_ih, W_hh, b_ih, b_hh);

    // K9: zq = query_g @ Wih^T + bz  [2048,1024]
    hmma_gemm<0,128,0><<<dim3(1024/64, BQ/128), 256, SMEM_BM128>>>(sep, Wihp, bz, nullptr, zq, nullptr, BQ, 1024, 3*D);

    lstm_step1<<<(BQ * D) / 256, 256>>>();
    for (int s = 1; s < STEPS; s++) {
        hmma_gemm<0,128,0><<<dim3(1024/64, BQ/128), 256, SMEM_BM128>>>(hp, Whhp, zs, zq, z, nullptr, BQ, 1024, 3*D);
        lstm_step<<<(BQ * D) / 256, 256>>>();
    }

    final_kernel<<<BQ, 256>>>(out);
}